// round 11
// baseline (speedup 1.0000x reference)
#include <cuda_runtime.h>
#include <cuda_bf16.h>
#include <math.h>

#define NEG_INF (-1e30f)
#define NB 16
#define LC 2048
#define LQ 512
#define DD 512
#define D4 2048

typedef __nv_bfloat16 bf16;

// bf16 scratch (converted once per launch)
__device__ bf16  g_Cb [NB * LC * DD];
__device__ bf16  g_Qb [NB * LQ * DD];
__device__ bf16  g_Qtb[NB * DD * LQ];
__device__ bf16  g_W1b[DD * DD];
__device__ bf16  g_Wfb[D4 * D4];
__device__ bf16  g_Wgb[D4 * D4];
__device__ bf16  g_Cpb[NB * LC * DD];
__device__ bf16  g_Qpb[NB * LQ * DD];
__device__ float g_S  [NB * LC * LQ];
__device__ bf16  g_Sb [NB * LC * LQ];
__device__ bf16  g_catb[(size_t)NB * LC * D4];   // materialized cat (compacted rows)
__device__ int   g_idx[NB * LC];
__device__ int   g_cnt[NB];

// ---------------------------------------------------------------------------
__device__ __forceinline__ unsigned pk(float a, float b) {
    __nv_bfloat162 h = __floats2bfloat162_rn(a, b);
    return *reinterpret_cast<unsigned*>(&h);
}

__device__ __forceinline__ void mma_bf16(float* d, const unsigned* a, const unsigned* b) {
    asm volatile(
        "mma.sync.aligned.m16n8k16.row.col.f32.bf16.bf16.f32 "
        "{%0,%1,%2,%3}, {%4,%5,%6,%7}, {%8,%9}, {%0,%1,%2,%3};\n"
        : "+f"(d[0]), "+f"(d[1]), "+f"(d[2]), "+f"(d[3])
        : "r"(a[0]), "r"(a[1]), "r"(a[2]), "r"(a[3]), "r"(b[0]), "r"(b[1]));
}

__device__ __forceinline__ void ldsm4(unsigned* r, unsigned addr) {
    asm volatile("ldmatrix.sync.aligned.m8n8.x4.shared.b16 {%0,%1,%2,%3}, [%4];"
                 : "=r"(r[0]), "=r"(r[1]), "=r"(r[2]), "=r"(r[3]) : "r"(addr));
}

__device__ __forceinline__ unsigned sptr(const void* p) {
    return (unsigned)__cvta_generic_to_shared(p);
}

__device__ __forceinline__ void cpasync16(unsigned dst, const void* src) {
    asm volatile("cp.async.cg.shared.global [%0], [%1], 16;\n" :: "r"(dst), "l"(src));
}
__device__ __forceinline__ void cpcommit() {
    asm volatile("cp.async.commit_group;\n" ::: "memory");
}
template <int N> __device__ __forceinline__ void cpwait() {
    asm volatile("cp.async.wait_group %0;\n" :: "n"(N) : "memory");
}

// SMEM: row-major bf16 tiles, row stride = 5 x 16B chunks (80B).
// (5r + c) mod 8 permutes bank-groups -> ldmatrix conflict-free, no swizzle.
#define FCH (128 * 5)   // 128-row tile in uint4 units

// ---------------------------------------------------------------------------
__global__ void compact_kernel(const int* __restrict__ Cmask) {
    __shared__ int toff[257];
    int b = blockIdx.x;
    int t = threadIdx.x;
    int flags[8];
    int s = 0;
#pragma unroll
    for (int i = 0; i < 8; i++) {
        flags[i] = (Cmask[b * LC + t * 8 + i] != 0) ? 1 : 0;
        s += flags[i];
    }
    toff[t + 1] = s;
    __syncthreads();
    if (t == 0) {
        toff[0] = 0;
        for (int i = 1; i <= 256; i++) toff[i] += toff[i - 1];
        g_cnt[b] = toff[256];
    }
    __syncthreads();
    int pos = toff[t];
#pragma unroll
    for (int i = 0; i < 8; i++) {
        if (flags[i]) g_idx[b * LC + (pos++)] = t * 8 + i;
    }
}

__global__ void fill_masked_kernel(const int* __restrict__ Cmask,
                                   float* __restrict__ out) {
    int c = blockIdx.y;
    int b = blockIdx.z;
    if (Cmask[b * LC + c] != 0) return;
    float4* p = (float4*)(out + ((size_t)(b * LC + c)) * D4);
    float4 v = make_float4(NEG_INF, NEG_INF, NEG_INF, NEG_INF);
    int t = threadIdx.x;
    p[t] = v; p[t + 128] = v; p[t + 256] = v; p[t + 384] = v;
}

// fp32 -> bf16 bulk convert (8 elems / thread)
__global__ void cvt_kernel(const float* __restrict__ src, bf16* __restrict__ dst,
                           int n8) {
    int i = blockIdx.x * blockDim.x + threadIdx.x;
    if (i >= n8) return;
    const float4* s = (const float4*)src + (size_t)i * 2;
    float4 a = s[0], b = s[1];
    uint4 o;
    o.x = pk(a.x, a.y); o.y = pk(a.z, a.w);
    o.z = pk(b.x, b.y); o.w = pk(b.z, b.w);
    ((uint4*)dst)[i] = o;
}

// Q fp32 -> transposed bf16: g_Qtb[b][d][q]
__global__ void transpose_q_kernel(const float* __restrict__ Q) {
    __shared__ float t[32][33];
    int b = blockIdx.z;
    int d0 = blockIdx.x * 32, q0 = blockIdx.y * 32;
    int tx = threadIdx.x, ty = threadIdx.y;
#pragma unroll
    for (int i = 0; i < 4; i++)
        t[ty + i * 8][tx] = Q[((size_t)b * LQ + q0 + ty + i * 8) * DD + d0 + tx];
    __syncthreads();
#pragma unroll
    for (int i = 0; i < 4; i++)
        g_Qtb[((size_t)b * DD + d0 + ty + i * 8) * LQ + q0 + tx] =
            __float2bfloat16(t[tx][ty + i * 8]);
}

// ---------------------------------------------------------------------------
// Generic bf16 NT GEMM: BM=128 BN=128 BK=32, 512 threads (16 warps, 4m x 4n),
// 3-stage cp.async pipeline, ldmatrix consumer, dynamic smem (60KB).
// mode 0: bias + leaky_relu -> bf16; mode 1: fp32 out; mode 2: bf16 out;
// mode 3: write all 4 cat segments of g_catb (attn fusion; Yv unused).
// ---------------------------------------------------------------------------
__global__ __launch_bounds__(512, 1)
void gemm512(const bf16* __restrict__ A, int lda, int Arows_per_b,
             const bf16* __restrict__ B, int ldb, int Brows_per_b,
             void* __restrict__ Yv, int ldy,
             const float* __restrict__ bias,
             int K, int Mfull, int use_cnt, int gather, int mode) {
    int b  = blockIdx.z;
    int m0 = blockIdx.y * 128;
    int n0 = blockIdx.x * 128;
    int M  = use_cnt ? g_cnt[b] : Mfull;
    if (m0 >= M) return;

    extern __shared__ __align__(16) uint4 dynG[];
    uint4* sA = dynG;            // [3][FCH]
    uint4* sB = dynG + 3 * FCH;  // [3][FCH]

    int tid = threadIdx.x;
    int ar = tid >> 2, ac = tid & 3;   // 128 rows x 4 chunks, 1 chunk/thread

    int j = min(m0 + ar, M - 1);
    int srow = gather ? g_idx[b * LC + j] : j;
    const bf16* Asrc = A + ((size_t)b * Arows_per_b + srow) * lda + ac * 8;
    const bf16* Bsrc = B + ((size_t)b * Brows_per_b + n0 + ar) * ldb + ac * 8;
    unsigned dst0 = (unsigned)(ar * 5 + ac) * 16;
    unsigned adst0 = sptr(sA) + dst0;
    unsigned bdst0 = sptr(sB) + dst0;

    int lane = tid & 31, w = tid >> 5;
    int wm = w >> 2, wn = w & 3;
    int a_off = (wm * 32 + (lane & 15)) * 5 + (lane >> 4);
    int b_off = (wn * 32 + ((lane >> 4) << 3) + (lane & 7)) * 5 + ((lane >> 3) & 1);

    float acc[2][4][4];
#pragma unroll
    for (int mi = 0; mi < 2; mi++)
#pragma unroll
        for (int ni = 0; ni < 4; ni++)
#pragma unroll
            for (int r = 0; r < 4; r++) acc[mi][ni][r] = 0.f;

    const int KIT = K / 32;

#define GISSUE(it_)                                                         \
    {                                                                       \
        int st_ = (it_) % 3;                                                \
        unsigned so_ = (unsigned)st_ * (FCH * 16);                          \
        cpasync16(adst0 + so_, Asrc + (it_) * 32);                          \
        cpasync16(bdst0 + so_, Bsrc + (it_) * 32);                          \
    }

    GISSUE(0); cpcommit();
    if (KIT > 1) { GISSUE(1); } cpcommit();

    for (int it = 0; it < KIT; it++) {
        cpwait<1>();
        __syncthreads();
        if (it + 2 < KIT) { GISSUE(it + 2); }
        cpcommit();
        int st = it % 3;
        unsigned abase = sptr(sA) + (unsigned)st * (FCH * 16);
        unsigned bbase = sptr(sB) + (unsigned)st * (FCH * 16);
#pragma unroll
        for (int ks = 0; ks < 2; ks++) {
            unsigned av[2][4], bv[2][4];
#pragma unroll
            for (int mi = 0; mi < 2; mi++)
                ldsm4(av[mi], abase + (unsigned)(a_off + mi * 16 * 5 + ks * 2) * 16);
#pragma unroll
            for (int np = 0; np < 2; np++)
                ldsm4(bv[np], bbase + (unsigned)(b_off + np * 16 * 5 + ks * 2) * 16);
#pragma unroll
            for (int mi = 0; mi < 2; mi++)
#pragma unroll
                for (int ni = 0; ni < 4; ni++) {
                    unsigned bb[2] = { bv[ni >> 1][(ni & 1) * 2 + 0],
                                       bv[ni >> 1][(ni & 1) * 2 + 1] };
                    mma_bf16(acc[mi][ni], av[mi], bb);
                }
        }
    }
#undef GISSUE

    int gid = lane >> 2, tig = lane & 3;
#pragma unroll
    for (int mi = 0; mi < 2; mi++) {
#pragma unroll
        for (int rr = 0; rr < 2; rr++) {
            int m = m0 + wm * 32 + mi * 16 + gid + rr * 8;
            if (m >= M) continue;
            if (mode == 1) {
                float* yr = (float*)Yv + ((size_t)b * Arows_per_b + m) * ldy;
#pragma unroll
                for (int ni = 0; ni < 4; ni++) {
                    int n = n0 + wn * 32 + ni * 8 + tig * 2;
                    yr[n]     = acc[mi][ni][rr * 2 + 0];
                    yr[n + 1] = acc[mi][ni][rr * 2 + 1];
                }
            } else if (mode == 3) {
                // cat fusion: acc = attn_C[m][n]; write [C | A | A-C | A*C]
                int c = g_idx[b * LC + m];
                const bf16* crow = g_Cb + ((size_t)b * LC + c) * DD;
                bf16* catrow = g_catb + ((size_t)b * LC + m) * D4;
#pragma unroll
                for (int ni = 0; ni < 4; ni++) {
                    int n = n0 + wn * 32 + ni * 8 + tig * 2;
                    float a0 = acc[mi][ni][rr * 2 + 0];
                    float a1 = acc[mi][ni][rr * 2 + 1];
                    __nv_bfloat162 c2 = *(const __nv_bfloat162*)(crow + n);
                    float c0 = __bfloat162float(c2.x);
                    float c1 = __bfloat162float(c2.y);
                    *(__nv_bfloat162*)(catrow + n) = c2;
                    *(__nv_bfloat162*)(catrow + 512 + n)  = __floats2bfloat162_rn(a0, a1);
                    *(__nv_bfloat162*)(catrow + 1024 + n) = __floats2bfloat162_rn(a0 - c0, a1 - c1);
                    *(__nv_bfloat162*)(catrow + 1536 + n) = __floats2bfloat162_rn(a0 * c0, a1 * c1);
                }
            } else {
                bf16* yr = (bf16*)Yv + ((size_t)b * Arows_per_b + m) * ldy;
#pragma unroll
                for (int ni = 0; ni < 4; ni++) {
                    int n = n0 + wn * 32 + ni * 8 + tig * 2;
                    float v0 = acc[mi][ni][rr * 2 + 0];
                    float v1 = acc[mi][ni][rr * 2 + 1];
                    if (mode == 0) {
                        v0 += bias[n];     v1 += bias[n + 1];
                        v0 = (v0 > 0.f) ? v0 : 0.01f * v0;
                        v1 = (v1 > 0.f) ? v1 : 0.01f * v1;
                    }
                    *(__nv_bfloat162*)(yr + n) = __floats2bfloat162_rn(v0, v1);
                }
            }
        }
    }
}

// ---------------------------------------------------------------------------
// Softmax over q with Qmask: reads fp32 g_S, writes bf16 g_Sb.
// ---------------------------------------------------------------------------
__global__ void softmax_kernel(const int* __restrict__ Qmask) {
    int b = blockIdx.y, j = blockIdx.x;
    if (j >= g_cnt[b]) return;
    const float* row = g_S + ((size_t)b * LC + j) * LQ;
    bf16* orow = g_Sb + ((size_t)b * LC + j) * LQ;
    int t = threadIdx.x;
    int lane = t & 31, warp = t >> 5;
    float v0 = row[t];
    float v1 = row[t + 256];
    if (Qmask[b * LQ + t] == 0) v0 = NEG_INF;
    if (Qmask[b * LQ + t + 256] == 0) v1 = NEG_INF;

    __shared__ float red[8];
    __shared__ float bcast;

    float m = fmaxf(v0, v1);
#pragma unroll
    for (int o = 16; o; o >>= 1) m = fmaxf(m, __shfl_xor_sync(0xffffffffu, m, o));
    if (lane == 0) red[warp] = m;
    __syncthreads();
    if (t < 32) {
        float x = (t < 8) ? red[t] : -3.4e38f;
#pragma unroll
        for (int o = 4; o; o >>= 1) x = fmaxf(x, __shfl_xor_sync(0xffffffffu, x, o));
        if (t == 0) bcast = x;
    }
    __syncthreads();
    m = bcast;
    float e0 = expf(v0 - m), e1 = expf(v1 - m);
    float sum = e0 + e1;
#pragma unroll
    for (int o = 16; o; o >>= 1) sum += __shfl_xor_sync(0xffffffffu, sum, o);
    __syncthreads();
    if (lane == 0) red[warp] = sum;
    __syncthreads();
    if (t < 32) {
        float x = (t < 8) ? red[t] : 0.f;
#pragma unroll
        for (int o = 4; o; o >>= 1) x += __shfl_xor_sync(0xffffffffu, x, o);
        if (t == 0) bcast = x;
    }
    __syncthreads();
    float inv = 1.0f / bcast;
    orow[t]       = __float2bfloat16(e0 * inv);
    orow[t + 256] = __float2bfloat16(e1 * inv);
}

// ---------------------------------------------------------------------------
// Final fused dual GEMM on materialized cat: BM=128, BN=128, BK=32,
// 512 threads (16 warps = 4m x 4n, warp tile 32x32), 3-stage cp.async,
// dynamic smem (90KB). Epilogue: tanh/sigmoid/blend, gathered output rows.
// ---------------------------------------------------------------------------
__global__ __launch_bounds__(512, 1)
void final_mma3(const float* __restrict__ bfv, const float* __restrict__ bgv,
                float* __restrict__ out) {
    int b  = blockIdx.z;
    int m0 = blockIdx.y * 128;
    int n0 = blockIdx.x * 128;
    int M  = g_cnt[b];
    if (m0 >= M) return;

    extern __shared__ __align__(16) uint4 dyn[];
    uint4* sA  = dyn;              // [3][FCH]
    uint4* sBf = dyn + 3 * FCH;    // [3][FCH]
    uint4* sBg = dyn + 6 * FCH;    // [3][FCH]

    int tid = threadIdx.x;
    int ar = tid >> 2, ac = tid & 3;

    int j = min(m0 + ar, M - 1);
    const bf16* Asrc  = g_catb + ((size_t)b * LC + j) * D4 + ac * 8;
    const bf16* Bfsrc = g_Wfb + (size_t)(n0 + ar) * D4 + ac * 8;
    const bf16* Bgsrc = g_Wgb + (size_t)(n0 + ar) * D4 + ac * 8;
    unsigned dst0 = (unsigned)(ar * 5 + ac) * 16;
    unsigned adst0  = sptr(sA)  + dst0;
    unsigned bfdst0 = sptr(sBf) + dst0;
    unsigned bgdst0 = sptr(sBg) + dst0;

    int lane = tid & 31, w = tid >> 5;
    int wm = w >> 2, wn = w & 3;
    int a_off = (wm * 32 + (lane & 15)) * 5 + (lane >> 4);
    int b_off = (wn * 32 + ((lane >> 4) << 3) + (lane & 7)) * 5 + ((lane >> 3) & 1);

    float accf[2][4][4], accg[2][4][4];
#pragma unroll
    for (int mi = 0; mi < 2; mi++)
#pragma unroll
        for (int ni = 0; ni < 4; ni++)
#pragma unroll
            for (int r = 0; r < 4; r++) { accf[mi][ni][r] = 0.f; accg[mi][ni][r] = 0.f; }

    const int KIT = D4 / 32;   // 64

#define FISSUE(it_)                                                          \
    {                                                                        \
        int st_ = (it_) % 3;                                                 \
        unsigned so_ = (unsigned)st_ * (FCH * 16);                           \
        cpasync16(adst0 + so_,  Asrc + (it_) * 32);                          \
        cpasync16(bfdst0 + so_, Bfsrc + (it_) * 32);                         \
        cpasync16(bgdst0 + so_, Bgsrc + (it_) * 32);                         \
    }

    FISSUE(0); cpcommit();
    FISSUE(1); cpcommit();

    for (int it = 0; it < KIT; it++) {
        cpwait<1>();
        __syncthreads();
        if (it + 2 < KIT) { FISSUE(it + 2); }
        cpcommit();
        int st = it % 3;
        unsigned abase  = sptr(sA)  + (unsigned)st * (FCH * 16);
        unsigned bfbase = sptr(sBf) + (unsigned)st * (FCH * 16);
        unsigned bgbase = sptr(sBg) + (unsigned)st * (FCH * 16);
#pragma unroll
        for (int ks = 0; ks < 2; ks++) {
            unsigned av[2][4], bvf[2][4], bvg[2][4];
#pragma unroll
            for (int mi = 0; mi < 2; mi++)
                ldsm4(av[mi], abase + (unsigned)(a_off + mi * 16 * 5 + ks * 2) * 16);
#pragma unroll
            for (int np = 0; np < 2; np++) {
                ldsm4(bvf[np], bfbase + (unsigned)(b_off + np * 16 * 5 + ks * 2) * 16);
                ldsm4(bvg[np], bgbase + (unsigned)(b_off + np * 16 * 5 + ks * 2) * 16);
            }
#pragma unroll
            for (int mi = 0; mi < 2; mi++)
#pragma unroll
                for (int ni = 0; ni < 4; ni++) {
                    unsigned bf2[2] = { bvf[ni >> 1][(ni & 1) * 2 + 0],
                                        bvf[ni >> 1][(ni & 1) * 2 + 1] };
                    unsigned bg2[2] = { bvg[ni >> 1][(ni & 1) * 2 + 0],
                                        bvg[ni >> 1][(ni & 1) * 2 + 1] };
                    mma_bf16(accf[mi][ni], av[mi], bf2);
                    mma_bf16(accg[mi][ni], av[mi], bg2);
                }
        }
    }
#undef FISSUE

    int gid = lane >> 2, tig = lane & 3;
#pragma unroll
    for (int mi = 0; mi < 2; mi++) {
#pragma unroll
        for (int rr = 0; rr < 2; rr++) {
            int jrow = m0 + wm * 32 + mi * 16 + gid + rr * 8;
            if (jrow < M) {
                int c = g_idx[b * LC + jrow];
                const bf16* catrow = g_catb + ((size_t)b * LC + jrow) * D4;
                float* orow = out + ((size_t)b * LC + c) * (size_t)D4;
#pragma unroll
                for (int ni = 0; ni < 4; ni++) {
                    int n = n0 + wn * 32 + ni * 8 + tig * 2;
                    __nv_bfloat162 cat2 = *(const __nv_bfloat162*)(catrow + n);
#pragma unroll
                    for (int e = 0; e < 2; e++) {
                        float catv = __bfloat162float(e ? cat2.y : cat2.x);
                        float df = accf[mi][ni][rr * 2 + e];
                        float dg = accg[mi][ni][rr * 2 + e];
                        float fv = tanhf(df + bfv[n + e]);
                        float gv = 1.0f / (1.0f + __expf(-(dg + bgv[n + e])));
                        orow[n + e] = gv * fv + (1.0f - gv) * catv;
                    }
                }
            }
        }
    }
}

// ---------------------------------------------------------------------------
extern "C" void kernel_launch(void* const* d_in, const int* in_sizes, int n_in,
                              void* d_out, int out_size) {
    const float* C     = (const float*)d_in[0];
    const float* Q     = (const float*)d_in[1];
    const int*   Cmask = (const int*)d_in[2];
    const int*   Qmask = (const int*)d_in[3];
    const float* W1    = (const float*)d_in[4];
    const float* b1    = (const float*)d_in[5];
    const float* Wf    = (const float*)d_in[6];
    const float* bfv   = (const float*)d_in[7];
    const float* Wg    = (const float*)d_in[8];
    const float* bgv   = (const float*)d_in[9];
    float* out = (float*)d_out;

    bf16* dCb;  cudaGetSymbolAddress((void**)&dCb,  g_Cb);
    bf16* dQb;  cudaGetSymbolAddress((void**)&dQb,  g_Qb);
    bf16* dQtb; cudaGetSymbolAddress((void**)&dQtb, g_Qtb);
    bf16* dW1b; cudaGetSymbolAddress((void**)&dW1b, g_W1b);
    bf16* dWfb; cudaGetSymbolAddress((void**)&dWfb, g_Wfb);
    bf16* dWgb; cudaGetSymbolAddress((void**)&dWgb, g_Wgb);
    bf16* dCpb; cudaGetSymbolAddress((void**)&dCpb, g_Cpb);
    bf16* dQpb; cudaGetSymbolAddress((void**)&dQpb, g_Qpb);
    float* dS;  cudaGetSymbolAddress((void**)&dS,   g_S);
    bf16* dSb;  cudaGetSymbolAddress((void**)&dSb,  g_Sb);

    const int GEMM_SMEM  = 6 * FCH * 16;   // 61440 B
    const int FINAL_SMEM = 9 * FCH * 16;   // 92160 B
    cudaFuncSetAttribute(gemm512,
                         cudaFuncAttributeMaxDynamicSharedMemorySize, GEMM_SMEM);
    cudaFuncSetAttribute(final_mma3,
                         cudaFuncAttributeMaxDynamicSharedMemorySize, FINAL_SMEM);

    compact_kernel<<<NB, 256>>>(Cmask);
    fill_masked_kernel<<<dim3(1, LC, NB), 128>>>(Cmask, out);

    // one-time fp32 -> bf16 conversions
    cvt_kernel<<<(NB * LC * DD / 8 + 255) / 256, 256>>>(C,  dCb,  NB * LC * DD / 8);
    cvt_kernel<<<(NB * LQ * DD / 8 + 255) / 256, 256>>>(Q,  dQb,  NB * LQ * DD / 8);
    cvt_kernel<<<(DD * DD / 8 + 255) / 256, 256>>>(W1, dW1b, DD * DD / 8);
    cvt_kernel<<<(D4 * D4 / 8 + 255) / 256, 256>>>(Wf, dWfb, D4 * D4 / 8);
    cvt_kernel<<<(D4 * D4 / 8 + 255) / 256, 256>>>(Wg, dWgb, D4 * D4 / 8);
    transpose_q_kernel<<<dim3(DD / 32, LQ / 32, NB), dim3(32, 8)>>>(Q);

    // C_ = lrelu(C@W1^T + b1), compacted rows
    gemm512<<<dim3(DD / 128, LC / 128, NB), 512, GEMM_SMEM>>>(
        dCb, DD, LC, dW1b, DD, 0, dCpb, DD, b1, DD, LC, 1, 1, 0);
    // Q_ = lrelu(Q@W1^T + b1), all rows
    gemm512<<<dim3(DD / 128, LQ / 128, NB), 512, GEMM_SMEM>>>(
        dQb, DD, LQ, dW1b, DD, 0, dQpb, DD, b1, DD, LQ, 0, 0, 0);
    // S = C_ @ Q_^T (compacted c; batched B) -> fp32
    gemm512<<<dim3(LQ / 128, LC / 128, NB), 512, GEMM_SMEM>>>(
        dCpb, DD, LC, dQpb, DD, LQ, dS, LQ, b1, DD, LC, 1, 0, 1);
    // masked softmax -> bf16 probabilities
    softmax_kernel<<<dim3(LC, NB), 256>>>(Qmask);
    // attn_C = S_ @ Qt^T (compacted c; batched B) -> fused cat write (mode 3)
    gemm512<<<dim3(DD / 128, LC / 128, NB), 512, GEMM_SMEM>>>(
        dSb, LQ, LC, dQtb, LQ, DD, (void*)0, DD, b1, LQ, LC, 1, 0, 3);
    // fused dual GEMM + blend epilogue on materialized cat
    final_mma3<<<dim3(D4 / 128, LC / 128, NB), 512, FINAL_SMEM>>>(bfv, bgv, out);
}

// round 14
// speedup vs baseline: 1.4976x; 1.4976x over previous
#include <cuda_runtime.h>
#include <cuda_bf16.h>
#include <math.h>

#define NEG_INF (-1e30f)
#define NB 16
#define LC 2048
#define LQ 512
#define DD 512
#define D4 2048

typedef __nv_bfloat16 bf16;

// bf16 scratch (converted once per launch)
__device__ bf16  g_Cb [NB * LC * DD];
__device__ bf16  g_Qb [NB * LQ * DD];
__device__ bf16  g_Qtb[NB * DD * LQ];
__device__ bf16  g_W1b[DD * DD];
__device__ bf16  g_Wfb[D4 * D4];
__device__ bf16  g_Wgb[D4 * D4];
__device__ bf16  g_Cpb[NB * LC * DD];
__device__ bf16  g_Qpb[NB * LQ * DD];
__device__ bf16  g_Sb [NB * LC * LQ];            // raw scores, then probabilities
__device__ bf16  g_catb[(size_t)NB * LC * D4];   // materialized cat (compacted rows)
__device__ int   g_idx[NB * LC];
__device__ int   g_cnt[NB];

// ---------------------------------------------------------------------------
__device__ __forceinline__ unsigned pk(float a, float b) {
    __nv_bfloat162 h = __floats2bfloat162_rn(a, b);
    return *reinterpret_cast<unsigned*>(&h);
}

__device__ __forceinline__ void mma_bf16(float* d, const unsigned* a, const unsigned* b) {
    asm volatile(
        "mma.sync.aligned.m16n8k16.row.col.f32.bf16.bf16.f32 "
        "{%0,%1,%2,%3}, {%4,%5,%6,%7}, {%8,%9}, {%0,%1,%2,%3};\n"
        : "+f"(d[0]), "+f"(d[1]), "+f"(d[2]), "+f"(d[3])
        : "r"(a[0]), "r"(a[1]), "r"(a[2]), "r"(a[3]), "r"(b[0]), "r"(b[1]));
}

__device__ __forceinline__ void ldsm4(unsigned* r, unsigned addr) {
    asm volatile("ldmatrix.sync.aligned.m8n8.x4.shared.b16 {%0,%1,%2,%3}, [%4];"
                 : "=r"(r[0]), "=r"(r[1]), "=r"(r[2]), "=r"(r[3]) : "r"(addr));
}

__device__ __forceinline__ unsigned sptr(const void* p) {
    return (unsigned)__cvta_generic_to_shared(p);
}

__device__ __forceinline__ void cpasync16(unsigned dst, const void* src) {
    asm volatile("cp.async.cg.shared.global [%0], [%1], 16;\n" :: "r"(dst), "l"(src));
}
__device__ __forceinline__ void cpcommit() {
    asm volatile("cp.async.commit_group;\n" ::: "memory");
}
template <int N> __device__ __forceinline__ void cpwait() {
    asm volatile("cp.async.wait_group %0;\n" :: "n"(N) : "memory");
}

// SMEM: row-major bf16 tiles, row stride = 5 x 16B chunks (80B).
// (5r + c) mod 8 permutes bank-groups -> ldmatrix conflict-free, no swizzle.
#define ACH (128 * 5)
#define BCH (64 * 5)
#define FCH (128 * 5)   // final kernel tiles: 128 rows

// ---------------------------------------------------------------------------
__global__ void compact_kernel(const int* __restrict__ Cmask) {
    __shared__ int toff[257];
    int b = blockIdx.x;
    int t = threadIdx.x;
    int flags[8];
    int s = 0;
#pragma unroll
    for (int i = 0; i < 8; i++) {
        flags[i] = (Cmask[b * LC + t * 8 + i] != 0) ? 1 : 0;
        s += flags[i];
    }
    toff[t + 1] = s;
    __syncthreads();
    if (t == 0) {
        toff[0] = 0;
        for (int i = 1; i <= 256; i++) toff[i] += toff[i - 1];
        g_cnt[b] = toff[256];
    }
    __syncthreads();
    int pos = toff[t];
#pragma unroll
    for (int i = 0; i < 8; i++) {
        if (flags[i]) g_idx[b * LC + (pos++)] = t * 8 + i;
    }
}

__global__ void fill_masked_kernel(const int* __restrict__ Cmask,
                                   float* __restrict__ out) {
    int c = blockIdx.y;
    int b = blockIdx.z;
    if (Cmask[b * LC + c] != 0) return;
    float4* p = (float4*)(out + ((size_t)(b * LC + c)) * D4);
    float4 v = make_float4(NEG_INF, NEG_INF, NEG_INF, NEG_INF);
    int t = threadIdx.x;
    p[t] = v; p[t + 128] = v; p[t + 256] = v; p[t + 384] = v;
}

// fp32 -> bf16 bulk convert (8 elems / thread)
__global__ void cvt_kernel(const float* __restrict__ src, bf16* __restrict__ dst,
                           int n8) {
    int i = blockIdx.x * blockDim.x + threadIdx.x;
    if (i >= n8) return;
    const float4* s = (const float4*)src + (size_t)i * 2;
    float4 a = s[0], b = s[1];
    uint4 o;
    o.x = pk(a.x, a.y); o.y = pk(a.z, a.w);
    o.z = pk(b.x, b.y); o.w = pk(b.z, b.w);
    ((uint4*)dst)[i] = o;
}

// Q fp32 -> transposed bf16: g_Qtb[b][d][q]
__global__ void transpose_q_kernel(const float* __restrict__ Q) {
    __shared__ float t[32][33];
    int b = blockIdx.z;
    int d0 = blockIdx.x * 32, q0 = blockIdx.y * 32;
    int tx = threadIdx.x, ty = threadIdx.y;
#pragma unroll
    for (int i = 0; i < 4; i++)
        t[ty + i * 8][tx] = Q[((size_t)b * LQ + q0 + ty + i * 8) * DD + d0 + tx];
    __syncthreads();
#pragma unroll
    for (int i = 0; i < 4; i++)
        g_Qtb[((size_t)b * DD + d0 + ty + i * 8) * LQ + q0 + tx] =
            __float2bfloat16(t[tx][ty + i * 8]);
}

// ---------------------------------------------------------------------------
// Generic bf16 NT GEMM: 3-stage cp.async pipeline, ldmatrix consumer.
// BM=128 BN=64 BK=32, 256 threads (8 warps = 4m x 2n of 32x32).
// mode 0: bias + leaky_relu -> bf16; mode 2: bf16 out;
// mode 3: acc = attn_C -> write all 4 cat segments of g_catb (Yv unused).
// ---------------------------------------------------------------------------
__global__ __launch_bounds__(256, 2)
void gemm_bf16(const bf16* __restrict__ A, int lda, int Arows_per_b,
               const bf16* __restrict__ B, int ldb, int Brows_per_b,
               void* __restrict__ Yv, int ldy,
               const float* __restrict__ bias,
               int K, int Mfull, int use_cnt, int gather, int mode) {
    int b  = blockIdx.z;
    int m0 = blockIdx.y * 128;
    int n0 = blockIdx.x * 64;
    int M  = use_cnt ? g_cnt[b] : Mfull;
    if (m0 >= M) return;

    __shared__ __align__(16) uint4 sA[3][ACH];
    __shared__ __align__(16) uint4 sB[3][BCH];

    int tid = threadIdx.x;
    int ar = tid >> 1, ac = (tid & 1) * 2;
    int br = tid >> 2, bc = tid & 3;
    int j = min(m0 + ar, M - 1);
    int srow = gather ? g_idx[b * LC + j] : j;
    const bf16* Asrc = A + ((size_t)b * Arows_per_b + srow) * lda + ac * 8;
    const bf16* Bsrc = B + ((size_t)b * Brows_per_b + n0 + br) * ldb + bc * 8;
    unsigned adst0 = sptr(&sA[0][0]) + (unsigned)(ar * 5 + ac) * 16;
    unsigned bdst0 = sptr(&sB[0][0]) + (unsigned)(br * 5 + bc) * 16;

    int lane = tid & 31, w = tid >> 5;
    int wm = w >> 1, wn = w & 1;
    int a_off = (wm * 32 + (lane & 15)) * 5 + (lane >> 4);
    int b_off = (wn * 32 + ((lane >> 4) << 3) + (lane & 7)) * 5 + ((lane >> 3) & 1);

    float acc[2][4][4];
#pragma unroll
    for (int mi = 0; mi < 2; mi++)
#pragma unroll
        for (int ni = 0; ni < 4; ni++)
#pragma unroll
            for (int r = 0; r < 4; r++) acc[mi][ni][r] = 0.f;

    const int KIT = K / 32;

#define ISSUE(it_)                                                          \
    {                                                                       \
        int st_ = (it_) % 3;                                                \
        cpasync16(adst0 + (unsigned)st_ * (ACH * 16), Asrc + (it_) * 32);   \
        cpasync16(adst0 + (unsigned)st_ * (ACH * 16) + 16,                  \
                  Asrc + (it_) * 32 + 8);                                   \
        cpasync16(bdst0 + (unsigned)st_ * (BCH * 16), Bsrc + (it_) * 32);   \
    }

    ISSUE(0); cpcommit();
    if (KIT > 1) { ISSUE(1); } cpcommit();

    for (int it = 0; it < KIT; it++) {
        cpwait<1>();
        __syncthreads();
        if (it + 2 < KIT) { ISSUE(it + 2); }
        cpcommit();
        int st = it % 3;
        unsigned abase = sptr(&sA[st][0]);
        unsigned bbase = sptr(&sB[st][0]);
#pragma unroll
        for (int ks = 0; ks < 2; ks++) {
            unsigned av[2][4], bv[2][4];
#pragma unroll
            for (int mi = 0; mi < 2; mi++)
                ldsm4(av[mi], abase + (unsigned)(a_off + mi * 16 * 5 + ks * 2) * 16);
#pragma unroll
            for (int np = 0; np < 2; np++)
                ldsm4(bv[np], bbase + (unsigned)(b_off + np * 16 * 5 + ks * 2) * 16);
#pragma unroll
            for (int mi = 0; mi < 2; mi++)
#pragma unroll
                for (int ni = 0; ni < 4; ni++) {
                    unsigned bb[2] = { bv[ni >> 1][(ni & 1) * 2 + 0],
                                       bv[ni >> 1][(ni & 1) * 2 + 1] };
                    mma_bf16(acc[mi][ni], av[mi], bb);
                }
        }
    }
#undef ISSUE

    int gid = lane >> 2, tig = lane & 3;
#pragma unroll
    for (int mi = 0; mi < 2; mi++) {
#pragma unroll
        for (int rr = 0; rr < 2; rr++) {
            int m = m0 + wm * 32 + mi * 16 + gid + rr * 8;
            if (m >= M) continue;
            if (mode == 3) {
                // cat fusion: acc = attn_C[m][n]; write [C | A | A-C | A*C]
                int c = g_idx[b * LC + m];
                const bf16* crow = g_Cb + ((size_t)b * LC + c) * DD;
                bf16* catrow = g_catb + ((size_t)b * LC + m) * D4;
#pragma unroll
                for (int ni = 0; ni < 4; ni++) {
                    int n = n0 + wn * 32 + ni * 8 + tig * 2;
                    float a0 = acc[mi][ni][rr * 2 + 0];
                    float a1 = acc[mi][ni][rr * 2 + 1];
                    __nv_bfloat162 c2 = *(const __nv_bfloat162*)(crow + n);
                    float c0 = __bfloat162float(c2.x);
                    float c1 = __bfloat162float(c2.y);
                    *(__nv_bfloat162*)(catrow + n)        = c2;
                    *(__nv_bfloat162*)(catrow + 512 + n)  = __floats2bfloat162_rn(a0, a1);
                    *(__nv_bfloat162*)(catrow + 1024 + n) = __floats2bfloat162_rn(a0 - c0, a1 - c1);
                    *(__nv_bfloat162*)(catrow + 1536 + n) = __floats2bfloat162_rn(a0 * c0, a1 * c1);
                }
            } else {
                bf16* yr = (bf16*)Yv + ((size_t)b * Arows_per_b + m) * ldy;
#pragma unroll
                for (int ni = 0; ni < 4; ni++) {
                    int n = n0 + wn * 32 + ni * 8 + tig * 2;
                    float v0 = acc[mi][ni][rr * 2 + 0];
                    float v1 = acc[mi][ni][rr * 2 + 1];
                    if (mode == 0) {
                        v0 += bias[n];     v1 += bias[n + 1];
                        v0 = (v0 > 0.f) ? v0 : 0.01f * v0;
                        v1 = (v1 > 0.f) ? v1 : 0.01f * v1;
                    }
                    *(__nv_bfloat162*)(yr + n) = __floats2bfloat162_rn(v0, v1);
                }
            }
        }
    }
}

// ---------------------------------------------------------------------------
// Softmax over q with Qmask: reads bf16 raw scores from g_Sb, writes bf16
// probabilities in place.
// ---------------------------------------------------------------------------
__global__ void softmax_kernel(const int* __restrict__ Qmask) {
    int b = blockIdx.y, j = blockIdx.x;
    if (j >= g_cnt[b]) return;
    bf16* row = g_Sb + ((size_t)b * LC + j) * LQ;
    int t = threadIdx.x;
    int lane = t & 31, warp = t >> 5;
    float v0 = __bfloat162float(row[t]);
    float v1 = __bfloat162float(row[t + 256]);
    if (Qmask[b * LQ + t] == 0) v0 = NEG_INF;
    if (Qmask[b * LQ + t + 256] == 0) v1 = NEG_INF;

    __shared__ float red[8];
    __shared__ float bcast;

    float m = fmaxf(v0, v1);
#pragma unroll
    for (int o = 16; o; o >>= 1) m = fmaxf(m, __shfl_xor_sync(0xffffffffu, m, o));
    if (lane == 0) red[warp] = m;
    __syncthreads();
    if (t < 32) {
        float x = (t < 8) ? red[t] : -3.4e38f;
#pragma unroll
        for (int o = 4; o; o >>= 1) x = fmaxf(x, __shfl_xor_sync(0xffffffffu, x, o));
        if (t == 0) bcast = x;
    }
    __syncthreads();
    m = bcast;
    float e0 = expf(v0 - m), e1 = expf(v1 - m);
    float sum = e0 + e1;
#pragma unroll
    for (int o = 16; o; o >>= 1) sum += __shfl_xor_sync(0xffffffffu, sum, o);
    __syncthreads();
    if (lane == 0) red[warp] = sum;
    __syncthreads();
    if (t < 32) {
        float x = (t < 8) ? red[t] : 0.f;
#pragma unroll
        for (int o = 4; o; o >>= 1) x += __shfl_xor_sync(0xffffffffu, x, o);
        if (t == 0) bcast = x;
    }
    __syncthreads();
    float inv = 1.0f / bcast;
    row[t]       = __float2bfloat16(e0 * inv);
    row[t + 256] = __float2bfloat16(e1 * inv);
}

// ---------------------------------------------------------------------------
// Final fused dual GEMM on materialized cat: BM=128, BN=128, BK=32,
// 512 threads (16 warps = 4m x 4n, warp tile 32x32), 3-stage cp.async,
// dynamic smem (90KB). Epilogue: tanh/sigmoid/blend, gathered output rows.
// ---------------------------------------------------------------------------
__global__ __launch_bounds__(512, 1)
void final_mma3(const float* __restrict__ bfv, const float* __restrict__ bgv,
                float* __restrict__ out) {
    int b  = blockIdx.z;
    int m0 = blockIdx.y * 128;
    int n0 = blockIdx.x * 128;
    int M  = g_cnt[b];
    if (m0 >= M) return;

    extern __shared__ __align__(16) uint4 dyn[];
    uint4* sA  = dyn;              // [3][FCH]
    uint4* sBf = dyn + 3 * FCH;    // [3][FCH]
    uint4* sBg = dyn + 6 * FCH;    // [3][FCH]

    int tid = threadIdx.x;
    int ar = tid >> 2, ac = tid & 3;

    int j = min(m0 + ar, M - 1);
    const bf16* Asrc  = g_catb + ((size_t)b * LC + j) * D4 + ac * 8;
    const bf16* Bfsrc = g_Wfb + (size_t)(n0 + ar) * D4 + ac * 8;
    const bf16* Bgsrc = g_Wgb + (size_t)(n0 + ar) * D4 + ac * 8;
    unsigned dst0 = (unsigned)(ar * 5 + ac) * 16;
    unsigned adst0  = sptr(sA)  + dst0;
    unsigned bfdst0 = sptr(sBf) + dst0;
    unsigned bgdst0 = sptr(sBg) + dst0;

    int lane = tid & 31, w = tid >> 5;
    int wm = w >> 2, wn = w & 3;
    int a_off = (wm * 32 + (lane & 15)) * 5 + (lane >> 4);
    int b_off = (wn * 32 + ((lane >> 4) << 3) + (lane & 7)) * 5 + ((lane >> 3) & 1);

    float accf[2][4][4], accg[2][4][4];
#pragma unroll
    for (int mi = 0; mi < 2; mi++)
#pragma unroll
        for (int ni = 0; ni < 4; ni++)
#pragma unroll
            for (int r = 0; r < 4; r++) { accf[mi][ni][r] = 0.f; accg[mi][ni][r] = 0.f; }

    const int KIT = D4 / 32;   // 64

#define FISSUE(it_)                                                          \
    {                                                                        \
        int st_ = (it_) % 3;                                                 \
        unsigned so_ = (unsigned)st_ * (FCH * 16);                           \
        cpasync16(adst0 + so_,  Asrc + (it_) * 32);                          \
        cpasync16(bfdst0 + so_, Bfsrc + (it_) * 32);                         \
        cpasync16(bgdst0 + so_, Bgsrc + (it_) * 32);                         \
    }

    FISSUE(0); cpcommit();
    FISSUE(1); cpcommit();

    for (int it = 0; it < KIT; it++) {
        cpwait<1>();
        __syncthreads();
        if (it + 2 < KIT) { FISSUE(it + 2); }
        cpcommit();
        int st = it % 3;
        unsigned abase  = sptr(sA)  + (unsigned)st * (FCH * 16);
        unsigned bfbase = sptr(sBf) + (unsigned)st * (FCH * 16);
        unsigned bgbase = sptr(sBg) + (unsigned)st * (FCH * 16);
#pragma unroll
        for (int ks = 0; ks < 2; ks++) {
            unsigned av[2][4], bvf[2][4], bvg[2][4];
#pragma unroll
            for (int mi = 0; mi < 2; mi++)
                ldsm4(av[mi], abase + (unsigned)(a_off + mi * 16 * 5 + ks * 2) * 16);
#pragma unroll
            for (int np = 0; np < 2; np++) {
                ldsm4(bvf[np], bfbase + (unsigned)(b_off + np * 16 * 5 + ks * 2) * 16);
                ldsm4(bvg[np], bgbase + (unsigned)(b_off + np * 16 * 5 + ks * 2) * 16);
            }
#pragma unroll
            for (int mi = 0; mi < 2; mi++)
#pragma unroll
                for (int ni = 0; ni < 4; ni++) {
                    unsigned bf2[2] = { bvf[ni >> 1][(ni & 1) * 2 + 0],
                                        bvf[ni >> 1][(ni & 1) * 2 + 1] };
                    unsigned bg2[2] = { bvg[ni >> 1][(ni & 1) * 2 + 0],
                                        bvg[ni >> 1][(ni & 1) * 2 + 1] };
                    mma_bf16(accf[mi][ni], av[mi], bf2);
                    mma_bf16(accg[mi][ni], av[mi], bg2);
                }
        }
    }
#undef FISSUE

    int gid = lane >> 2, tig = lane & 3;
#pragma unroll
    for (int mi = 0; mi < 2; mi++) {
#pragma unroll
        for (int rr = 0; rr < 2; rr++) {
            int jrow = m0 + wm * 32 + mi * 16 + gid + rr * 8;
            if (jrow < M) {
                int c = g_idx[b * LC + jrow];
                const bf16* catrow = g_catb + ((size_t)b * LC + jrow) * D4;
                float* orow = out + ((size_t)b * LC + c) * (size_t)D4;
#pragma unroll
                for (int ni = 0; ni < 4; ni++) {
                    int n = n0 + wn * 32 + ni * 8 + tig * 2;
                    __nv_bfloat162 cat2 = *(const __nv_bfloat162*)(catrow + n);
#pragma unroll
                    for (int e = 0; e < 2; e++) {
                        float catv = __bfloat162float(e ? cat2.y : cat2.x);
                        float df = accf[mi][ni][rr * 2 + e];
                        float dg = accg[mi][ni][rr * 2 + e];
                        float fv = tanhf(df + bfv[n + e]);
                        float gv = 1.0f / (1.0f + __expf(-(dg + bgv[n + e])));
                        orow[n + e] = gv * fv + (1.0f - gv) * catv;
                    }
                }
            }
        }
    }
}

// ---------------------------------------------------------------------------
extern "C" void kernel_launch(void* const* d_in, const int* in_sizes, int n_in,
                              void* d_out, int out_size) {
    const float* C     = (const float*)d_in[0];
    const float* Q     = (const float*)d_in[1];
    const int*   Cmask = (const int*)d_in[2];
    const int*   Qmask = (const int*)d_in[3];
    const float* W1    = (const float*)d_in[4];
    const float* b1    = (const float*)d_in[5];
    const float* Wf    = (const float*)d_in[6];
    const float* bfv   = (const float*)d_in[7];
    const float* Wg    = (const float*)d_in[8];
    const float* bgv   = (const float*)d_in[9];
    float* out = (float*)d_out;

    bf16* dCb;  cudaGetSymbolAddress((void**)&dCb,  g_Cb);
    bf16* dQb;  cudaGetSymbolAddress((void**)&dQb,  g_Qb);
    bf16* dQtb; cudaGetSymbolAddress((void**)&dQtb, g_Qtb);
    bf16* dW1b; cudaGetSymbolAddress((void**)&dW1b, g_W1b);
    bf16* dWfb; cudaGetSymbolAddress((void**)&dWfb, g_Wfb);
    bf16* dWgb; cudaGetSymbolAddress((void**)&dWgb, g_Wgb);
    bf16* dCpb; cudaGetSymbolAddress((void**)&dCpb, g_Cpb);
    bf16* dQpb; cudaGetSymbolAddress((void**)&dQpb, g_Qpb);
    bf16* dSb;  cudaGetSymbolAddress((void**)&dSb,  g_Sb);

    const int FINAL_SMEM = 9 * FCH * 16;   // 92160 B
    cudaFuncSetAttribute(final_mma3,
                         cudaFuncAttributeMaxDynamicSharedMemorySize, FINAL_SMEM);

    compact_kernel<<<NB, 256>>>(Cmask);
    fill_masked_kernel<<<dim3(1, LC, NB), 128>>>(Cmask, out);

    // one-time fp32 -> bf16 conversions
    cvt_kernel<<<(NB * LC * DD / 8 + 255) / 256, 256>>>(C,  dCb,  NB * LC * DD / 8);
    cvt_kernel<<<(NB * LQ * DD / 8 + 255) / 256, 256>>>(Q,  dQb,  NB * LQ * DD / 8);
    cvt_kernel<<<(DD * DD / 8 + 255) / 256, 256>>>(W1, dW1b, DD * DD / 8);
    cvt_kernel<<<(D4 * D4 / 8 + 255) / 256, 256>>>(Wf, dWfb, D4 * D4 / 8);
    cvt_kernel<<<(D4 * D4 / 8 + 255) / 256, 256>>>(Wg, dWgb, D4 * D4 / 8);
    transpose_q_kernel<<<dim3(DD / 32, LQ / 32, NB), dim3(32, 8)>>>(Q);

    // C_ = lrelu(C@W1^T + b1), compacted rows
    gemm_bf16<<<dim3(DD / 64, LC / 128, NB), 256>>>(
        dCb, DD, LC, dW1b, DD, 0, dCpb, DD, b1, DD, LC, 1, 1, 0);
    // Q_ = lrelu(Q@W1^T + b1), all rows
    gemm_bf16<<<dim3(DD / 64, LQ / 128, NB), 256>>>(
        dQb, DD, LQ, dW1b, DD, 0, dQpb, DD, b1, DD, LQ, 0, 0, 0);
    // S = C_ @ Q_^T (compacted c; batched B) -> bf16 raw scores
    gemm_bf16<<<dim3(LQ / 64, LC / 128, NB), 256>>>(
        dCpb, DD, LC, dQpb, DD, LQ, dSb, LQ, b1, DD, LC, 1, 0, 2);
    // masked softmax in place on g_Sb
    softmax_kernel<<<dim3(LC, NB), 256>>>(Qmask);
    // attn_C = S_ @ Qt^T (compacted c; batched B) -> fused cat write (mode 3)
    gemm_bf16<<<dim3(DD / 64, LC / 128, NB), 256>>>(
        dSb, LQ, LC, dQtb, LQ, DD, (void*)0, DD, b1, LQ, LC, 1, 0, 3);
    // fused dual GEMM + blend epilogue on materialized cat
    final_mma3<<<dim3(D4 / 128, LC / 128, NB), 512, FINAL_SMEM>>>(bfv, bgv, out);
}

// round 15
// speedup vs baseline: 1.6409x; 1.0957x over previous
#include <cuda_runtime.h>
#include <cuda_bf16.h>
#include <cuda_fp8.h>
#include <math.h>

#define NEG_INF (-1e30f)
#define NB 16
#define LC 2048
#define LQ 512
#define DD 512
#define D4 2048

typedef __nv_bfloat16 bf16;

// scratch (converted once per launch)
__device__ bf16  g_Cb [NB * LC * DD];
__device__ bf16  g_Qb [NB * LQ * DD];
__device__ bf16  g_Qtb[NB * DD * LQ];
__device__ bf16  g_W1b[DD * DD];
__device__ bf16  g_Cpb[NB * LC * DD];
__device__ bf16  g_Qpb[NB * LQ * DD];
__device__ bf16  g_Sb [NB * LC * LQ];                     // scores -> probs
__device__ unsigned char g_cat8[(size_t)NB * LC * D4];    // cat, e4m3
__device__ unsigned char g_Wf8[(size_t)D4 * D4];          // Wf * 16, e4m3
__device__ unsigned char g_Wg8[(size_t)D4 * D4];          // Wg * 16, e4m3
__device__ int   g_idx[NB * LC];
__device__ int   g_cnt[NB];

#define W8SCALE 16.0f
#define W8INV   0.0625f

// ---------------------------------------------------------------------------
__device__ __forceinline__ unsigned pk(float a, float b) {
    __nv_bfloat162 h = __floats2bfloat162_rn(a, b);
    return *reinterpret_cast<unsigned*>(&h);
}

__device__ __forceinline__ unsigned short pk8x2(float a, float b) {
    __nv_fp8x2_e4m3 p(make_float2(a, b));
    return *reinterpret_cast<unsigned short*>(&p);
}

__device__ __forceinline__ void mma_bf16(float* d, const unsigned* a, const unsigned* b) {
    asm volatile(
        "mma.sync.aligned.m16n8k16.row.col.f32.bf16.bf16.f32 "
        "{%0,%1,%2,%3}, {%4,%5,%6,%7}, {%8,%9}, {%0,%1,%2,%3};\n"
        : "+f"(d[0]), "+f"(d[1]), "+f"(d[2]), "+f"(d[3])
        : "r"(a[0]), "r"(a[1]), "r"(a[2]), "r"(a[3]), "r"(b[0]), "r"(b[1]));
}

__device__ __forceinline__ void mma_fp8(float* d, const unsigned* a, const unsigned* b) {
    asm volatile(
        "mma.sync.aligned.m16n8k32.row.col.f32.e4m3.e4m3.f32 "
        "{%0,%1,%2,%3}, {%4,%5,%6,%7}, {%8,%9}, {%0,%1,%2,%3};\n"
        : "+f"(d[0]), "+f"(d[1]), "+f"(d[2]), "+f"(d[3])
        : "r"(a[0]), "r"(a[1]), "r"(a[2]), "r"(a[3]), "r"(b[0]), "r"(b[1]));
}

__device__ __forceinline__ void ldsm4(unsigned* r, unsigned addr) {
    asm volatile("ldmatrix.sync.aligned.m8n8.x4.shared.b16 {%0,%1,%2,%3}, [%4];"
                 : "=r"(r[0]), "=r"(r[1]), "=r"(r[2]), "=r"(r[3]) : "r"(addr));
}

__device__ __forceinline__ unsigned sptr(const void* p) {
    return (unsigned)__cvta_generic_to_shared(p);
}

__device__ __forceinline__ void cpasync16(unsigned dst, const void* src) {
    asm volatile("cp.async.cg.shared.global [%0], [%1], 16;\n" :: "r"(dst), "l"(src));
}
__device__ __forceinline__ void cpcommit() {
    asm volatile("cp.async.commit_group;\n" ::: "memory");
}
template <int N> __device__ __forceinline__ void cpwait() {
    asm volatile("cp.async.wait_group %0;\n" :: "n"(N) : "memory");
}

// SMEM: row-major tiles, row stride = 5 x 16B chunks (80B).
// (5r + c) mod 8 permutes bank-groups -> ldmatrix conflict-free, no swizzle.
#define ACH (128 * 5)
#define BCH (64 * 5)
#define FCH (128 * 5)

// ---------------------------------------------------------------------------
__global__ void compact_kernel(const int* __restrict__ Cmask) {
    __shared__ int toff[257];
    int b = blockIdx.x;
    int t = threadIdx.x;
    int flags[8];
    int s = 0;
#pragma unroll
    for (int i = 0; i < 8; i++) {
        flags[i] = (Cmask[b * LC + t * 8 + i] != 0) ? 1 : 0;
        s += flags[i];
    }
    toff[t + 1] = s;
    __syncthreads();
    if (t == 0) {
        toff[0] = 0;
        for (int i = 1; i <= 256; i++) toff[i] += toff[i - 1];
        g_cnt[b] = toff[256];
    }
    __syncthreads();
    int pos = toff[t];
#pragma unroll
    for (int i = 0; i < 8; i++) {
        if (flags[i]) g_idx[b * LC + (pos++)] = t * 8 + i;
    }
}

__global__ void fill_masked_kernel(const int* __restrict__ Cmask,
                                   float* __restrict__ out) {
    int c = blockIdx.y;
    int b = blockIdx.z;
    if (Cmask[b * LC + c] != 0) return;
    float4* p = (float4*)(out + ((size_t)(b * LC + c)) * D4);
    float4 v = make_float4(NEG_INF, NEG_INF, NEG_INF, NEG_INF);
    int t = threadIdx.x;
    p[t] = v; p[t + 128] = v; p[t + 256] = v; p[t + 384] = v;
}

// fp32 -> bf16 bulk convert (8 elems / thread)
__global__ void cvt_kernel(const float* __restrict__ src, bf16* __restrict__ dst,
                           int n8) {
    int i = blockIdx.x * blockDim.x + threadIdx.x;
    if (i >= n8) return;
    const float4* s = (const float4*)src + (size_t)i * 2;
    float4 a = s[0], b = s[1];
    uint4 o;
    o.x = pk(a.x, a.y); o.y = pk(a.z, a.w);
    o.z = pk(b.x, b.y); o.w = pk(b.z, b.w);
    ((uint4*)dst)[i] = o;
}

// fp32 -> e4m3 (scaled) bulk convert (16 elems / thread)
__global__ void cvt8_kernel(const float* __restrict__ src,
                            unsigned char* __restrict__ dst, int n16, float sc) {
    int i = blockIdx.x * blockDim.x + threadIdx.x;
    if (i >= n16) return;
    const float4* s = (const float4*)src + (size_t)i * 4;
    uint4 o;
    unsigned* op = &o.x;
#pragma unroll
    for (int q = 0; q < 4; q++) {
        float4 f = s[q];
        __nv_fp8x4_e4m3 p(make_float4(f.x * sc, f.y * sc, f.z * sc, f.w * sc));
        op[q] = *reinterpret_cast<unsigned*>(&p);
    }
    ((uint4*)dst)[i] = o;
}

// Q fp32 -> transposed bf16: g_Qtb[b][d][q]
__global__ void transpose_q_kernel(const float* __restrict__ Q) {
    __shared__ float t[32][33];
    int b = blockIdx.z;
    int d0 = blockIdx.x * 32, q0 = blockIdx.y * 32;
    int tx = threadIdx.x, ty = threadIdx.y;
#pragma unroll
    for (int i = 0; i < 4; i++)
        t[ty + i * 8][tx] = Q[((size_t)b * LQ + q0 + ty + i * 8) * DD + d0 + tx];
    __syncthreads();
#pragma unroll
    for (int i = 0; i < 4; i++)
        g_Qtb[((size_t)b * DD + d0 + ty + i * 8) * LQ + q0 + tx] =
            __float2bfloat16(t[tx][ty + i * 8]);
}

// ---------------------------------------------------------------------------
// Generic bf16 NT GEMM: 3-stage cp.async pipeline, ldmatrix consumer.
// BM=128 BN=64 BK=32, 256 threads (8 warps = 4m x 2n of 32x32).
// mode 0: bias + leaky_relu -> bf16; mode 2: bf16 out;
// mode 3: acc = attn_C -> write all 4 cat segments of g_cat8 (Yv unused).
// ---------------------------------------------------------------------------
__global__ __launch_bounds__(256, 2)
void gemm_bf16(const bf16* __restrict__ A, int lda, int Arows_per_b,
               const bf16* __restrict__ B, int ldb, int Brows_per_b,
               void* __restrict__ Yv, int ldy,
               const float* __restrict__ bias,
               int K, int Mfull, int use_cnt, int gather, int mode) {
    int b  = blockIdx.z;
    int m0 = blockIdx.y * 128;
    int n0 = blockIdx.x * 64;
    int M  = use_cnt ? g_cnt[b] : Mfull;
    if (m0 >= M) return;

    __shared__ __align__(16) uint4 sA[3][ACH];
    __shared__ __align__(16) uint4 sB[3][BCH];

    int tid = threadIdx.x;
    int ar = tid >> 1, ac = (tid & 1) * 2;
    int br = tid >> 2, bc = tid & 3;
    int j = min(m0 + ar, M - 1);
    int srow = gather ? g_idx[b * LC + j] : j;
    const bf16* Asrc = A + ((size_t)b * Arows_per_b + srow) * lda + ac * 8;
    const bf16* Bsrc = B + ((size_t)b * Brows_per_b + n0 + br) * ldb + bc * 8;
    unsigned adst0 = sptr(&sA[0][0]) + (unsigned)(ar * 5 + ac) * 16;
    unsigned bdst0 = sptr(&sB[0][0]) + (unsigned)(br * 5 + bc) * 16;

    int lane = tid & 31, w = tid >> 5;
    int wm = w >> 1, wn = w & 1;
    int a_off = (wm * 32 + (lane & 15)) * 5 + (lane >> 4);
    int b_off = (wn * 32 + ((lane >> 4) << 3) + (lane & 7)) * 5 + ((lane >> 3) & 1);

    float acc[2][4][4];
#pragma unroll
    for (int mi = 0; mi < 2; mi++)
#pragma unroll
        for (int ni = 0; ni < 4; ni++)
#pragma unroll
            for (int r = 0; r < 4; r++) acc[mi][ni][r] = 0.f;

    const int KIT = K / 32;

#define ISSUE(it_)                                                          \
    {                                                                       \
        int st_ = (it_) % 3;                                                \
        cpasync16(adst0 + (unsigned)st_ * (ACH * 16), Asrc + (it_) * 32);   \
        cpasync16(adst0 + (unsigned)st_ * (ACH * 16) + 16,                  \
                  Asrc + (it_) * 32 + 8);                                   \
        cpasync16(bdst0 + (unsigned)st_ * (BCH * 16), Bsrc + (it_) * 32);   \
    }

    ISSUE(0); cpcommit();
    if (KIT > 1) { ISSUE(1); } cpcommit();

    for (int it = 0; it < KIT; it++) {
        cpwait<1>();
        __syncthreads();
        if (it + 2 < KIT) { ISSUE(it + 2); }
        cpcommit();
        int st = it % 3;
        unsigned abase = sptr(&sA[st][0]);
        unsigned bbase = sptr(&sB[st][0]);
#pragma unroll
        for (int ks = 0; ks < 2; ks++) {
            unsigned av[2][4], bv[2][4];
#pragma unroll
            for (int mi = 0; mi < 2; mi++)
                ldsm4(av[mi], abase + (unsigned)(a_off + mi * 16 * 5 + ks * 2) * 16);
#pragma unroll
            for (int np = 0; np < 2; np++)
                ldsm4(bv[np], bbase + (unsigned)(b_off + np * 16 * 5 + ks * 2) * 16);
#pragma unroll
            for (int mi = 0; mi < 2; mi++)
#pragma unroll
                for (int ni = 0; ni < 4; ni++) {
                    unsigned bb[2] = { bv[ni >> 1][(ni & 1) * 2 + 0],
                                       bv[ni >> 1][(ni & 1) * 2 + 1] };
                    mma_bf16(acc[mi][ni], av[mi], bb);
                }
        }
    }
#undef ISSUE

    int gid = lane >> 2, tig = lane & 3;
#pragma unroll
    for (int mi = 0; mi < 2; mi++) {
#pragma unroll
        for (int rr = 0; rr < 2; rr++) {
            int m = m0 + wm * 32 + mi * 16 + gid + rr * 8;
            if (m >= M) continue;
            if (mode == 3) {
                // cat fusion: acc = attn_C[m][n]; write e4m3 [C | A | A-C | A*C]
                int c = g_idx[b * LC + m];
                const bf16* crow = g_Cb + ((size_t)b * LC + c) * DD;
                unsigned char* catrow = g_cat8 + ((size_t)b * LC + m) * D4;
#pragma unroll
                for (int ni = 0; ni < 4; ni++) {
                    int n = n0 + wn * 32 + ni * 8 + tig * 2;
                    float a0 = acc[mi][ni][rr * 2 + 0];
                    float a1 = acc[mi][ni][rr * 2 + 1];
                    __nv_bfloat162 c2 = *(const __nv_bfloat162*)(crow + n);
                    float c0 = __bfloat162float(c2.x);
                    float c1 = __bfloat162float(c2.y);
                    *(unsigned short*)(catrow + n)        = pk8x2(c0, c1);
                    *(unsigned short*)(catrow + 512 + n)  = pk8x2(a0, a1);
                    *(unsigned short*)(catrow + 1024 + n) = pk8x2(a0 - c0, a1 - c1);
                    *(unsigned short*)(catrow + 1536 + n) = pk8x2(a0 * c0, a1 * c1);
                }
            } else {
                bf16* yr = (bf16*)Yv + ((size_t)b * Arows_per_b + m) * ldy;
#pragma unroll
                for (int ni = 0; ni < 4; ni++) {
                    int n = n0 + wn * 32 + ni * 8 + tig * 2;
                    float v0 = acc[mi][ni][rr * 2 + 0];
                    float v1 = acc[mi][ni][rr * 2 + 1];
                    if (mode == 0) {
                        v0 += bias[n];     v1 += bias[n + 1];
                        v0 = (v0 > 0.f) ? v0 : 0.01f * v0;
                        v1 = (v1 > 0.f) ? v1 : 0.01f * v1;
                    }
                    *(__nv_bfloat162*)(yr + n) = __floats2bfloat162_rn(v0, v1);
                }
            }
        }
    }
}

// ---------------------------------------------------------------------------
// Softmax over q with Qmask: bf16 in/out, in place on g_Sb.
// ---------------------------------------------------------------------------
__global__ void softmax_kernel(const int* __restrict__ Qmask) {
    int b = blockIdx.y, j = blockIdx.x;
    if (j >= g_cnt[b]) return;
    bf16* row = g_Sb + ((size_t)b * LC + j) * LQ;
    int t = threadIdx.x;
    int lane = t & 31, warp = t >> 5;
    float v0 = __bfloat162float(row[t]);
    float v1 = __bfloat162float(row[t + 256]);
    if (Qmask[b * LQ + t] == 0) v0 = NEG_INF;
    if (Qmask[b * LQ + t + 256] == 0) v1 = NEG_INF;

    __shared__ float red[8];
    __shared__ float bcast;

    float m = fmaxf(v0, v1);
#pragma unroll
    for (int o = 16; o; o >>= 1) m = fmaxf(m, __shfl_xor_sync(0xffffffffu, m, o));
    if (lane == 0) red[warp] = m;
    __syncthreads();
    if (t < 32) {
        float x = (t < 8) ? red[t] : -3.4e38f;
#pragma unroll
        for (int o = 4; o; o >>= 1) x = fmaxf(x, __shfl_xor_sync(0xffffffffu, x, o));
        if (t == 0) bcast = x;
    }
    __syncthreads();
    m = bcast;
    float e0 = expf(v0 - m), e1 = expf(v1 - m);
    float sum = e0 + e1;
#pragma unroll
    for (int o = 16; o; o >>= 1) sum += __shfl_xor_sync(0xffffffffu, sum, o);
    __syncthreads();
    if (lane == 0) red[warp] = sum;
    __syncthreads();
    if (t < 32) {
        float x = (t < 8) ? red[t] : 0.f;
#pragma unroll
        for (int o = 4; o; o >>= 1) x += __shfl_xor_sync(0xffffffffu, x, o);
        if (t == 0) bcast = x;
    }
    __syncthreads();
    float inv = 1.0f / bcast;
    row[t]       = __float2bfloat16(e0 * inv);
    row[t + 256] = __float2bfloat16(e1 * inv);
}

// ---------------------------------------------------------------------------
// Final fused dual GEMM, FP8 (e4m3): BM=128, BN=128, BK=64, KIT=32,
// 512 threads (16 warps = 4m x 4n, warp tile 32x32), 3-stage cp.async.
// Byte-layout identical to the bf16 version (64B/row/iter); fp8-pair == b16
// element isomorphism makes ldmatrix addressing carry over unchanged.
// Weights pre-scaled by 16 -> accumulators scaled back by 1/16 in epilogue.
// ---------------------------------------------------------------------------
__global__ __launch_bounds__(512, 1)
void final_fp8(const float* __restrict__ bfv, const float* __restrict__ bgv,
               float* __restrict__ out) {
    int b  = blockIdx.z;
    int m0 = blockIdx.y * 128;
    int n0 = blockIdx.x * 128;
    int M  = g_cnt[b];
    if (m0 >= M) return;

    extern __shared__ __align__(16) uint4 dyn[];
    uint4* sA  = dyn;              // [3][FCH]
    uint4* sBf = dyn + 3 * FCH;    // [3][FCH]
    uint4* sBg = dyn + 6 * FCH;    // [3][FCH]

    int tid = threadIdx.x;
    int ar = tid >> 2, ac = tid & 3;   // 128 rows x 4 chunks of 16B = 64B/row

    int j = min(m0 + ar, M - 1);
    const unsigned char* Asrc  = g_cat8 + ((size_t)b * LC + j) * D4 + ac * 16;
    const unsigned char* Bfsrc = g_Wf8 + (size_t)(n0 + ar) * D4 + ac * 16;
    const unsigned char* Bgsrc = g_Wg8 + (size_t)(n0 + ar) * D4 + ac * 16;
    unsigned dst0 = (unsigned)(ar * 5 + ac) * 16;
    unsigned adst0  = sptr(sA)  + dst0;
    unsigned bfdst0 = sptr(sBf) + dst0;
    unsigned bgdst0 = sptr(sBg) + dst0;

    int lane = tid & 31, w = tid >> 5;
    int wm = w >> 2, wn = w & 3;
    int a_off = (wm * 32 + (lane & 15)) * 5 + (lane >> 4);
    int b_off = (wn * 32 + ((lane >> 4) << 3) + (lane & 7)) * 5 + ((lane >> 3) & 1);

    float accf[2][4][4], accg[2][4][4];
#pragma unroll
    for (int mi = 0; mi < 2; mi++)
#pragma unroll
        for (int ni = 0; ni < 4; ni++)
#pragma unroll
            for (int r = 0; r < 4; r++) { accf[mi][ni][r] = 0.f; accg[mi][ni][r] = 0.f; }

    const int KIT = D4 / 64;   // 32 iterations of k=64 fp8

#define FISSUE(it_)                                                          \
    {                                                                        \
        int st_ = (it_) % 3;                                                 \
        unsigned so_ = (unsigned)st_ * (FCH * 16);                           \
        cpasync16(adst0 + so_,  Asrc + (it_) * 64);                          \
        cpasync16(bfdst0 + so_, Bfsrc + (it_) * 64);                         \
        cpasync16(bgdst0 + so_, Bgsrc + (it_) * 64);                         \
    }

    FISSUE(0); cpcommit();
    FISSUE(1); cpcommit();

    for (int it = 0; it < KIT; it++) {
        cpwait<1>();
        __syncthreads();
        if (it + 2 < KIT) { FISSUE(it + 2); }
        cpcommit();
        int st = it % 3;
        unsigned abase  = sptr(sA)  + (unsigned)st * (FCH * 16);
        unsigned bfbase = sptr(sBf) + (unsigned)st * (FCH * 16);
        unsigned bgbase = sptr(sBg) + (unsigned)st * (FCH * 16);
#pragma unroll
        for (int ks = 0; ks < 2; ks++) {   // 2 x k32 fp8 mma
            unsigned av[2][4], bvf[2][4], bvg[2][4];
#pragma unroll
            for (int mi = 0; mi < 2; mi++)
                ldsm4(av[mi], abase + (unsigned)(a_off + mi * 16 * 5 + ks * 2) * 16);
#pragma unroll
            for (int np = 0; np < 2; np++) {
                ldsm4(bvf[np], bfbase + (unsigned)(b_off + np * 16 * 5 + ks * 2) * 16);
                ldsm4(bvg[np], bgbase + (unsigned)(b_off + np * 16 * 5 + ks * 2) * 16);
            }
#pragma unroll
            for (int mi = 0; mi < 2; mi++)
#pragma unroll
                for (int ni = 0; ni < 4; ni++) {
                    unsigned bf2[2] = { bvf[ni >> 1][(ni & 1) * 2 + 0],
                                        bvf[ni >> 1][(ni & 1) * 2 + 1] };
                    unsigned bg2[2] = { bvg[ni >> 1][(ni & 1) * 2 + 0],
                                        bvg[ni >> 1][(ni & 1) * 2 + 1] };
                    mma_fp8(accf[mi][ni], av[mi], bf2);
                    mma_fp8(accg[mi][ni], av[mi], bg2);
                }
        }
    }
#undef FISSUE

    int gid = lane >> 2, tig = lane & 3;
#pragma unroll
    for (int mi = 0; mi < 2; mi++) {
#pragma unroll
        for (int rr = 0; rr < 2; rr++) {
            int jrow = m0 + wm * 32 + mi * 16 + gid + rr * 8;
            if (jrow < M) {
                int c = g_idx[b * LC + jrow];
                const __nv_fp8_e4m3* catrow =
                    (const __nv_fp8_e4m3*)(g_cat8 + ((size_t)b * LC + jrow) * D4);
                float* orow = out + ((size_t)b * LC + c) * (size_t)D4;
#pragma unroll
                for (int ni = 0; ni < 4; ni++) {
                    int n = n0 + wn * 32 + ni * 8 + tig * 2;
#pragma unroll
                    for (int e = 0; e < 2; e++) {
                        float catv = float(catrow[n + e]);
                        float df = accf[mi][ni][rr * 2 + e] * W8INV;
                        float dg = accg[mi][ni][rr * 2 + e] * W8INV;
                        float fv = tanhf(df + bfv[n + e]);
                        float gv = 1.0f / (1.0f + __expf(-(dg + bgv[n + e])));
                        orow[n + e] = gv * fv + (1.0f - gv) * catv;
                    }
                }
            }
        }
    }
}

// ---------------------------------------------------------------------------
extern "C" void kernel_launch(void* const* d_in, const int* in_sizes, int n_in,
                              void* d_out, int out_size) {
    const float* C     = (const float*)d_in[0];
    const float* Q     = (const float*)d_in[1];
    const int*   Cmask = (const int*)d_in[2];
    const int*   Qmask = (const int*)d_in[3];
    const float* W1    = (const float*)d_in[4];
    const float* b1    = (const float*)d_in[5];
    const float* Wf    = (const float*)d_in[6];
    const float* bfv   = (const float*)d_in[7];
    const float* Wg    = (const float*)d_in[8];
    const float* bgv   = (const float*)d_in[9];
    float* out = (float*)d_out;

    bf16* dCb;  cudaGetSymbolAddress((void**)&dCb,  g_Cb);
    bf16* dQb;  cudaGetSymbolAddress((void**)&dQb,  g_Qb);
    bf16* dQtb; cudaGetSymbolAddress((void**)&dQtb, g_Qtb);
    bf16* dW1b; cudaGetSymbolAddress((void**)&dW1b, g_W1b);
    bf16* dCpb; cudaGetSymbolAddress((void**)&dCpb, g_Cpb);
    bf16* dQpb; cudaGetSymbolAddress((void**)&dQpb, g_Qpb);
    bf16* dSb;  cudaGetSymbolAddress((void**)&dSb,  g_Sb);
    unsigned char* dWf8; cudaGetSymbolAddress((void**)&dWf8, g_Wf8);
    unsigned char* dWg8; cudaGetSymbolAddress((void**)&dWg8, g_Wg8);

    const int FINAL_SMEM = 9 * FCH * 16;   // 92160 B
    cudaFuncSetAttribute(final_fp8,
                         cudaFuncAttributeMaxDynamicSharedMemorySize, FINAL_SMEM);

    compact_kernel<<<NB, 256>>>(Cmask);
    fill_masked_kernel<<<dim3(1, LC, NB), 128>>>(Cmask, out);

    // one-time conversions
    cvt_kernel<<<(NB * LC * DD / 8 + 255) / 256, 256>>>(C,  dCb,  NB * LC * DD / 8);
    cvt_kernel<<<(NB * LQ * DD / 8 + 255) / 256, 256>>>(Q,  dQb,  NB * LQ * DD / 8);
    cvt_kernel<<<(DD * DD / 8 + 255) / 256, 256>>>(W1, dW1b, DD * DD / 8);
    cvt8_kernel<<<(D4 * D4 / 16 + 255) / 256, 256>>>(Wf, dWf8, D4 * D4 / 16, W8SCALE);
    cvt8_kernel<<<(D4 * D4 / 16 + 255) / 256, 256>>>(Wg, dWg8, D4 * D4 / 16, W8SCALE);
    transpose_q_kernel<<<dim3(DD / 32, LQ / 32, NB), dim3(32, 8)>>>(Q);

    // C_ = lrelu(C@W1^T + b1), compacted rows
    gemm_bf16<<<dim3(DD / 64, LC / 128, NB), 256>>>(
        dCb, DD, LC, dW1b, DD, 0, dCpb, DD, b1, DD, LC, 1, 1, 0);
    // Q_ = lrelu(Q@W1^T + b1), all rows
    gemm_bf16<<<dim3(DD / 64, LQ / 128, NB), 256>>>(
        dQb, DD, LQ, dW1b, DD, 0, dQpb, DD, b1, DD, LQ, 0, 0, 0);
    // S = C_ @ Q_^T (compacted c; batched B) -> bf16 raw scores
    gemm_bf16<<<dim3(LQ / 64, LC / 128, NB), 256>>>(
        dCpb, DD, LC, dQpb, DD, LQ, dSb, LQ, b1, DD, LC, 1, 0, 2);
    // masked softmax in place on g_Sb
    softmax_kernel<<<dim3(LC, NB), 256>>>(Qmask);
    // attn_C = S_ @ Qt^T (compacted c; batched B) -> fused e4m3 cat write
    gemm_bf16<<<dim3(DD / 64, LC / 128, NB), 256>>>(
        dSb, LQ, LC, dQtb, LQ, DD, (void*)0, DD, b1, LQ, LC, 1, 0, 3);
    // FP8 fused dual GEMM + blend epilogue
    final_fp8<<<dim3(D4 / 128, LC / 128, NB), 512, FINAL_SMEM>>>(bfv, bgv, out);
}

// round 16
// speedup vs baseline: 1.6872x; 1.0282x over previous
#include <cuda_runtime.h>
#include <cuda_bf16.h>
#include <cuda_fp8.h>
#include <math.h>

#define NEG_INF (-1e30f)
#define NB 16
#define LC 2048
#define LQ 512
#define DD 512
#define D4 2048

typedef __nv_bfloat16 bf16;
typedef unsigned char u8;

// fp8 scratch (converted once per launch)
__device__ u8    g_C8 [(size_t)NB * LC * DD];   // C, x1
__device__ u8    g_Q8 [(size_t)NB * LQ * DD];   // Q, x1
__device__ u8    g_Qt8[(size_t)NB * DD * LQ];   // Q^T, x16
__device__ u8    g_W18[(size_t)DD * DD];        // W1, x16
__device__ u8    g_Wf8[(size_t)D4 * D4];        // Wf, x16
__device__ u8    g_Wg8[(size_t)D4 * D4];        // Wg, x16
__device__ u8    g_Cp8[(size_t)NB * LC * DD];   // C_, x4
__device__ u8    g_Qp8[(size_t)NB * LQ * DD];   // Q_, x4
__device__ bf16  g_Sb [NB * LC * LQ];           // raw scores (bf16)
__device__ u8    g_P8 [(size_t)NB * LC * LQ];   // softmax probs, x16
__device__ u8    g_cat8[(size_t)NB * LC * D4];  // cat, e4m3 x1
__device__ int   g_idx[NB * LC];
__device__ int   g_cnt[NB];

#define W8INV 0.0625f   // 1/16

// ---------------------------------------------------------------------------
__device__ __forceinline__ unsigned pk(float a, float b) {
    __nv_bfloat162 h = __floats2bfloat162_rn(a, b);
    return *reinterpret_cast<unsigned*>(&h);
}

__device__ __forceinline__ unsigned short pk8x2(float a, float b) {
    __nv_fp8x2_e4m3 p(make_float2(a, b));
    return *reinterpret_cast<unsigned short*>(&p);
}

__device__ __forceinline__ void mma_fp8(float* d, const unsigned* a, const unsigned* b) {
    asm volatile(
        "mma.sync.aligned.m16n8k32.row.col.f32.e4m3.e4m3.f32 "
        "{%0,%1,%2,%3}, {%4,%5,%6,%7}, {%8,%9}, {%0,%1,%2,%3};\n"
        : "+f"(d[0]), "+f"(d[1]), "+f"(d[2]), "+f"(d[3])
        : "r"(a[0]), "r"(a[1]), "r"(a[2]), "r"(a[3]), "r"(b[0]), "r"(b[1]));
}

__device__ __forceinline__ void ldsm4(unsigned* r, unsigned addr) {
    asm volatile("ldmatrix.sync.aligned.m8n8.x4.shared.b16 {%0,%1,%2,%3}, [%4];"
                 : "=r"(r[0]), "=r"(r[1]), "=r"(r[2]), "=r"(r[3]) : "r"(addr));
}

__device__ __forceinline__ unsigned sptr(const void* p) {
    return (unsigned)__cvta_generic_to_shared(p);
}

__device__ __forceinline__ void cpasync16(unsigned dst, const void* src) {
    asm volatile("cp.async.cg.shared.global [%0], [%1], 16;\n" :: "r"(dst), "l"(src));
}
__device__ __forceinline__ void cpcommit() {
    asm volatile("cp.async.commit_group;\n" ::: "memory");
}
template <int N> __device__ __forceinline__ void cpwait() {
    asm volatile("cp.async.wait_group %0;\n" :: "n"(N) : "memory");
}

// SMEM: row-major tiles, row stride = 5 x 16B chunks (80B).
// (5r + c) mod 8 permutes bank-groups -> ldmatrix conflict-free, no swizzle.
#define ACH (128 * 5)
#define BCH (64 * 5)
#define FCH (128 * 5)

// ---------------------------------------------------------------------------
__global__ void compact_kernel(const int* __restrict__ Cmask) {
    __shared__ int toff[257];
    int b = blockIdx.x;
    int t = threadIdx.x;
    int flags[8];
    int s = 0;
#pragma unroll
    for (int i = 0; i < 8; i++) {
        flags[i] = (Cmask[b * LC + t * 8 + i] != 0) ? 1 : 0;
        s += flags[i];
    }
    toff[t + 1] = s;
    __syncthreads();
    if (t == 0) {
        toff[0] = 0;
        for (int i = 1; i <= 256; i++) toff[i] += toff[i - 1];
        g_cnt[b] = toff[256];
    }
    __syncthreads();
    int pos = toff[t];
#pragma unroll
    for (int i = 0; i < 8; i++) {
        if (flags[i]) g_idx[b * LC + (pos++)] = t * 8 + i;
    }
}

__global__ void fill_masked_kernel(const int* __restrict__ Cmask,
                                   float* __restrict__ out) {
    int c = blockIdx.y;
    int b = blockIdx.z;
    if (Cmask[b * LC + c] != 0) return;
    float4* p = (float4*)(out + ((size_t)(b * LC + c)) * D4);
    float4 v = make_float4(NEG_INF, NEG_INF, NEG_INF, NEG_INF);
    int t = threadIdx.x;
    p[t] = v; p[t + 128] = v; p[t + 256] = v; p[t + 384] = v;
}

// fp32 -> e4m3 (scaled) bulk convert (16 elems / thread)
__global__ void cvt8_kernel(const float* __restrict__ src,
                            u8* __restrict__ dst, int n16, float sc) {
    int i = blockIdx.x * blockDim.x + threadIdx.x;
    if (i >= n16) return;
    const float4* s = (const float4*)src + (size_t)i * 4;
    uint4 o;
    unsigned* op = &o.x;
#pragma unroll
    for (int q = 0; q < 4; q++) {
        float4 f = s[q];
        __nv_fp8x4_e4m3 p(make_float4(f.x * sc, f.y * sc, f.z * sc, f.w * sc));
        op[q] = *reinterpret_cast<unsigned*>(&p);
    }
    ((uint4*)dst)[i] = o;
}

// Q fp32 -> transposed e4m3 x16: g_Qt8[b][d][q]
__global__ void transpose_q8_kernel(const float* __restrict__ Q) {
    __shared__ float t[32][33];
    int b = blockIdx.z;
    int d0 = blockIdx.x * 32, q0 = blockIdx.y * 32;
    int tx = threadIdx.x, ty = threadIdx.y;
#pragma unroll
    for (int i = 0; i < 4; i++)
        t[ty + i * 8][tx] = Q[((size_t)b * LQ + q0 + ty + i * 8) * DD + d0 + tx];
    __syncthreads();
#pragma unroll
    for (int i = 0; i < 4; i++) {
        __nv_fp8_e4m3 v(t[tx][ty + i * 8] * 16.0f);
        g_Qt8[((size_t)b * DD + d0 + ty + i * 8) * LQ + q0 + tx] =
            *reinterpret_cast<u8*>(&v);
    }
}

// ---------------------------------------------------------------------------
// Generic e4m3 NT GEMM: 3-stage cp.async pipeline, ldmatrix consumer.
// BM=128 BN=64, 64B of K per iter (k64), 256 threads (8 warps = 4m x 2n).
// All pointers/strides in BYTES. K in fp8 elements.
// mode 0: v=acc*oscale+bias, leaky_relu, write e4m3 x wscale
// mode 2: write bf16 (acc*oscale)
// mode 3: acc*oscale = attn_C -> write 4 cat segments of g_cat8 (Yv unused)
// ---------------------------------------------------------------------------
__global__ __launch_bounds__(256, 2)
void gemm_fp8(const u8* __restrict__ A, int lda, int Arows_per_b,
              const u8* __restrict__ B, int ldb, int Brows_per_b,
              void* __restrict__ Yv, int ldy,
              const float* __restrict__ bias,
              int K, int Mfull, int use_cnt, int gather, int mode,
              float oscale, float wscale) {
    int b  = blockIdx.z;
    int m0 = blockIdx.y * 128;
    int n0 = blockIdx.x * 64;
    int M  = use_cnt ? g_cnt[b] : Mfull;
    if (m0 >= M) return;

    __shared__ __align__(16) uint4 sA[3][ACH];
    __shared__ __align__(16) uint4 sB[3][BCH];

    int tid = threadIdx.x;
    int ar = tid >> 1, ac = (tid & 1) * 2;   // 2x16B per thread, 64B/row
    int br = tid >> 2, bc = tid & 3;         // 4x16B per row
    int j = min(m0 + ar, M - 1);
    int srow = gather ? g_idx[b * LC + j] : j;
    const u8* Asrc = A + ((size_t)b * Arows_per_b + srow) * lda + ac * 16;
    const u8* Bsrc = B + ((size_t)b * Brows_per_b + n0 + br) * ldb + bc * 16;
    unsigned adst0 = sptr(&sA[0][0]) + (unsigned)(ar * 5 + ac) * 16;
    unsigned bdst0 = sptr(&sB[0][0]) + (unsigned)(br * 5 + bc) * 16;

    int lane = tid & 31, w = tid >> 5;
    int wm = w >> 1, wn = w & 1;
    int a_off = (wm * 32 + (lane & 15)) * 5 + (lane >> 4);
    int b_off = (wn * 32 + ((lane >> 4) << 3) + (lane & 7)) * 5 + ((lane >> 3) & 1);

    float acc[2][4][4];
#pragma unroll
    for (int mi = 0; mi < 2; mi++)
#pragma unroll
        for (int ni = 0; ni < 4; ni++)
#pragma unroll
            for (int r = 0; r < 4; r++) acc[mi][ni][r] = 0.f;

    const int KIT = K / 64;

#define ISSUE(it_)                                                          \
    {                                                                       \
        int st_ = (it_) % 3;                                                \
        cpasync16(adst0 + (unsigned)st_ * (ACH * 16), Asrc + (it_) * 64);   \
        cpasync16(adst0 + (unsigned)st_ * (ACH * 16) + 16,                  \
                  Asrc + (it_) * 64 + 16);                                  \
        cpasync16(bdst0 + (unsigned)st_ * (BCH * 16), Bsrc + (it_) * 64);   \
    }

    ISSUE(0); cpcommit();
    if (KIT > 1) { ISSUE(1); } cpcommit();

    for (int it = 0; it < KIT; it++) {
        cpwait<1>();
        __syncthreads();
        if (it + 2 < KIT) { ISSUE(it + 2); }
        cpcommit();
        int st = it % 3;
        unsigned abase = sptr(&sA[st][0]);
        unsigned bbase = sptr(&sB[st][0]);
#pragma unroll
        for (int ks = 0; ks < 2; ks++) {   // 2 x k32 fp8 mma
            unsigned av[2][4], bv[2][4];
#pragma unroll
            for (int mi = 0; mi < 2; mi++)
                ldsm4(av[mi], abase + (unsigned)(a_off + mi * 16 * 5 + ks * 2) * 16);
#pragma unroll
            for (int np = 0; np < 2; np++)
                ldsm4(bv[np], bbase + (unsigned)(b_off + np * 16 * 5 + ks * 2) * 16);
#pragma unroll
            for (int mi = 0; mi < 2; mi++)
#pragma unroll
                for (int ni = 0; ni < 4; ni++) {
                    unsigned bb[2] = { bv[ni >> 1][(ni & 1) * 2 + 0],
                                       bv[ni >> 1][(ni & 1) * 2 + 1] };
                    mma_fp8(acc[mi][ni], av[mi], bb);
                }
        }
    }
#undef ISSUE

    int gid = lane >> 2, tig = lane & 3;
#pragma unroll
    for (int mi = 0; mi < 2; mi++) {
#pragma unroll
        for (int rr = 0; rr < 2; rr++) {
            int m = m0 + wm * 32 + mi * 16 + gid + rr * 8;
            if (m >= M) continue;
            if (mode == 3) {
                // cat fusion: attn = acc*oscale; write e4m3 [C | A | A-C | A*C]
                int c = g_idx[b * LC + m];
                const __nv_fp8_e4m3* crow =
                    (const __nv_fp8_e4m3*)(g_C8 + ((size_t)b * LC + c) * DD);
                u8* catrow = g_cat8 + ((size_t)b * LC + m) * D4;
#pragma unroll
                for (int ni = 0; ni < 4; ni++) {
                    int n = n0 + wn * 32 + ni * 8 + tig * 2;
                    float a0 = acc[mi][ni][rr * 2 + 0] * oscale;
                    float a1 = acc[mi][ni][rr * 2 + 1] * oscale;
                    float c0 = float(crow[n]);
                    float c1 = float(crow[n + 1]);
                    *(unsigned short*)(catrow + n)        = pk8x2(c0, c1);
                    *(unsigned short*)(catrow + 512 + n)  = pk8x2(a0, a1);
                    *(unsigned short*)(catrow + 1024 + n) = pk8x2(a0 - c0, a1 - c1);
                    *(unsigned short*)(catrow + 1536 + n) = pk8x2(a0 * c0, a1 * c1);
                }
            } else if (mode == 0) {
                u8* yr = (u8*)Yv + ((size_t)b * Arows_per_b + m) * ldy;
#pragma unroll
                for (int ni = 0; ni < 4; ni++) {
                    int n = n0 + wn * 32 + ni * 8 + tig * 2;
                    float v0 = acc[mi][ni][rr * 2 + 0] * oscale + bias[n];
                    float v1 = acc[mi][ni][rr * 2 + 1] * oscale + bias[n + 1];
                    v0 = (v0 > 0.f) ? v0 : 0.01f * v0;
                    v1 = (v1 > 0.f) ? v1 : 0.01f * v1;
                    *(unsigned short*)(yr + n) = pk8x2(v0 * wscale, v1 * wscale);
                }
            } else {
                bf16* yr = (bf16*)Yv + ((size_t)b * Arows_per_b + m) * (size_t)ldy;
#pragma unroll
                for (int ni = 0; ni < 4; ni++) {
                    int n = n0 + wn * 32 + ni * 8 + tig * 2;
                    float v0 = acc[mi][ni][rr * 2 + 0] * oscale;
                    float v1 = acc[mi][ni][rr * 2 + 1] * oscale;
                    *(__nv_bfloat162*)(yr + n) = __floats2bfloat162_rn(v0, v1);
                }
            }
        }
    }
}

// ---------------------------------------------------------------------------
// Softmax over q with Qmask: bf16 scores in (g_Sb), e4m3 probs x16 out (g_P8).
// ---------------------------------------------------------------------------
__global__ void softmax_kernel(const int* __restrict__ Qmask) {
    int b = blockIdx.y, j = blockIdx.x;
    if (j >= g_cnt[b]) return;
    const bf16* row = g_Sb + ((size_t)b * LC + j) * LQ;
    u8* orow = g_P8 + ((size_t)b * LC + j) * LQ;
    int t = threadIdx.x;
    int lane = t & 31, warp = t >> 5;
    float v0 = __bfloat162float(row[t]);
    float v1 = __bfloat162float(row[t + 256]);
    if (Qmask[b * LQ + t] == 0) v0 = NEG_INF;
    if (Qmask[b * LQ + t + 256] == 0) v1 = NEG_INF;

    __shared__ float red[8];
    __shared__ float bcast;

    float m = fmaxf(v0, v1);
#pragma unroll
    for (int o = 16; o; o >>= 1) m = fmaxf(m, __shfl_xor_sync(0xffffffffu, m, o));
    if (lane == 0) red[warp] = m;
    __syncthreads();
    if (t < 32) {
        float x = (t < 8) ? red[t] : -3.4e38f;
#pragma unroll
        for (int o = 4; o; o >>= 1) x = fmaxf(x, __shfl_xor_sync(0xffffffffu, x, o));
        if (t == 0) bcast = x;
    }
    __syncthreads();
    m = bcast;
    float e0 = expf(v0 - m), e1 = expf(v1 - m);
    float sum = e0 + e1;
#pragma unroll
    for (int o = 16; o; o >>= 1) sum += __shfl_xor_sync(0xffffffffu, sum, o);
    __syncthreads();
    if (lane == 0) red[warp] = sum;
    __syncthreads();
    if (t < 32) {
        float x = (t < 8) ? red[t] : 0.f;
#pragma unroll
        for (int o = 4; o; o >>= 1) x += __shfl_xor_sync(0xffffffffu, x, o);
        if (t == 0) bcast = x;
    }
    __syncthreads();
    float inv = 16.0f / bcast;   // x16 for e4m3 storage
    __nv_fp8_e4m3 p0(e0 * inv), p1(e1 * inv);
    orow[t]       = *reinterpret_cast<u8*>(&p0);
    orow[t + 256] = *reinterpret_cast<u8*>(&p1);
}

// ---------------------------------------------------------------------------
// Final fused dual GEMM, FP8 (e4m3): BM=128, BN=128, k64/iter, KIT=32,
// 512 threads (16 warps = 4m x 4n, warp tile 32x32), 3-stage cp.async.
// Weights pre-scaled by 16 -> accumulators scaled back by 1/16 in epilogue.
// ---------------------------------------------------------------------------
__global__ __launch_bounds__(512, 1)
void final_fp8(const float* __restrict__ bfv, const float* __restrict__ bgv,
               float* __restrict__ out) {
    int b  = blockIdx.z;
    int m0 = blockIdx.y * 128;
    int n0 = blockIdx.x * 128;
    int M  = g_cnt[b];
    if (m0 >= M) return;

    extern __shared__ __align__(16) uint4 dyn[];
    uint4* sA  = dyn;              // [3][FCH]
    uint4* sBf = dyn + 3 * FCH;    // [3][FCH]
    uint4* sBg = dyn + 6 * FCH;    // [3][FCH]

    int tid = threadIdx.x;
    int ar = tid >> 2, ac = tid & 3;   // 128 rows x 4 chunks of 16B = 64B/row

    int j = min(m0 + ar, M - 1);
    const u8* Asrc  = g_cat8 + ((size_t)b * LC + j) * D4 + ac * 16;
    const u8* Bfsrc = g_Wf8 + (size_t)(n0 + ar) * D4 + ac * 16;
    const u8* Bgsrc = g_Wg8 + (size_t)(n0 + ar) * D4 + ac * 16;
    unsigned dst0 = (unsigned)(ar * 5 + ac) * 16;
    unsigned adst0  = sptr(sA)  + dst0;
    unsigned bfdst0 = sptr(sBf) + dst0;
    unsigned bgdst0 = sptr(sBg) + dst0;

    int lane = tid & 31, w = tid >> 5;
    int wm = w >> 2, wn = w & 3;
    int a_off = (wm * 32 + (lane & 15)) * 5 + (lane >> 4);
    int b_off = (wn * 32 + ((lane >> 4) << 3) + (lane & 7)) * 5 + ((lane >> 3) & 1);

    float accf[2][4][4], accg[2][4][4];
#pragma unroll
    for (int mi = 0; mi < 2; mi++)
#pragma unroll
        for (int ni = 0; ni < 4; ni++)
#pragma unroll
            for (int r = 0; r < 4; r++) { accf[mi][ni][r] = 0.f; accg[mi][ni][r] = 0.f; }

    const int KIT = D4 / 64;   // 32

#define FISSUE(it_)                                                          \
    {                                                                        \
        int st_ = (it_) % 3;                                                 \
        unsigned so_ = (unsigned)st_ * (FCH * 16);                           \
        cpasync16(adst0 + so_,  Asrc + (it_) * 64);                          \
        cpasync16(bfdst0 + so_, Bfsrc + (it_) * 64);                         \
        cpasync16(bgdst0 + so_, Bgsrc + (it_) * 64);                         \
    }

    FISSUE(0); cpcommit();
    FISSUE(1); cpcommit();

    for (int it = 0; it < KIT; it++) {
        cpwait<1>();
        __syncthreads();
        if (it + 2 < KIT) { FISSUE(it + 2); }
        cpcommit();
        int st = it % 3;
        unsigned abase  = sptr(sA)  + (unsigned)st * (FCH * 16);
        unsigned bfbase = sptr(sBf) + (unsigned)st * (FCH * 16);
        unsigned bgbase = sptr(sBg) + (unsigned)st * (FCH * 16);
#pragma unroll
        for (int ks = 0; ks < 2; ks++) {
            unsigned av[2][4], bvf[2][4], bvg[2][4];
#pragma unroll
            for (int mi = 0; mi < 2; mi++)
                ldsm4(av[mi], abase + (unsigned)(a_off + mi * 16 * 5 + ks * 2) * 16);
#pragma unroll
            for (int np = 0; np < 2; np++) {
                ldsm4(bvf[np], bfbase + (unsigned)(b_off + np * 16 * 5 + ks * 2) * 16);
                ldsm4(bvg[np], bgbase + (unsigned)(b_off + np * 16 * 5 + ks * 2) * 16);
            }
#pragma unroll
            for (int mi = 0; mi < 2; mi++)
#pragma unroll
                for (int ni = 0; ni < 4; ni++) {
                    unsigned bf2[2] = { bvf[ni >> 1][(ni & 1) * 2 + 0],
                                        bvf[ni >> 1][(ni & 1) * 2 + 1] };
                    unsigned bg2[2] = { bvg[ni >> 1][(ni & 1) * 2 + 0],
                                        bvg[ni >> 1][(ni & 1) * 2 + 1] };
                    mma_fp8(accf[mi][ni], av[mi], bf2);
                    mma_fp8(accg[mi][ni], av[mi], bg2);
                }
        }
    }
#undef FISSUE

    int gid = lane >> 2, tig = lane & 3;
#pragma unroll
    for (int mi = 0; mi < 2; mi++) {
#pragma unroll
        for (int rr = 0; rr < 2; rr++) {
            int jrow = m0 + wm * 32 + mi * 16 + gid + rr * 8;
            if (jrow < M) {
                int c = g_idx[b * LC + jrow];
                const __nv_fp8_e4m3* catrow =
                    (const __nv_fp8_e4m3*)(g_cat8 + ((size_t)b * LC + jrow) * D4);
                float* orow = out + ((size_t)b * LC + c) * (size_t)D4;
#pragma unroll
                for (int ni = 0; ni < 4; ni++) {
                    int n = n0 + wn * 32 + ni * 8 + tig * 2;
#pragma unroll
                    for (int e = 0; e < 2; e++) {
                        float catv = float(catrow[n + e]);
                        float df = accf[mi][ni][rr * 2 + e] * W8INV;
                        float dg = accg[mi][ni][rr * 2 + e] * W8INV;
                        float fv = tanhf(df + bfv[n + e]);
                        float gv = 1.0f / (1.0f + __expf(-(dg + bgv[n + e])));
                        orow[n + e] = gv * fv + (1.0f - gv) * catv;
                    }
                }
            }
        }
    }
}

// ---------------------------------------------------------------------------
extern "C" void kernel_launch(void* const* d_in, const int* in_sizes, int n_in,
                              void* d_out, int out_size) {
    const float* C     = (const float*)d_in[0];
    const float* Q     = (const float*)d_in[1];
    const int*   Cmask = (const int*)d_in[2];
    const int*   Qmask = (const int*)d_in[3];
    const float* W1    = (const float*)d_in[4];
    const float* b1    = (const float*)d_in[5];
    const float* Wf    = (const float*)d_in[6];
    const float* bfv   = (const float*)d_in[7];
    const float* Wg    = (const float*)d_in[8];
    const float* bgv   = (const float*)d_in[9];
    float* out = (float*)d_out;

    u8*   dC8;  cudaGetSymbolAddress((void**)&dC8,  g_C8);
    u8*   dQ8;  cudaGetSymbolAddress((void**)&dQ8,  g_Q8);
    u8*   dQt8; cudaGetSymbolAddress((void**)&dQt8, g_Qt8);
    u8*   dW18; cudaGetSymbolAddress((void**)&dW18, g_W18);
    u8*   dWf8; cudaGetSymbolAddress((void**)&dWf8, g_Wf8);
    u8*   dWg8; cudaGetSymbolAddress((void**)&dWg8, g_Wg8);
    u8*   dCp8; cudaGetSymbolAddress((void**)&dCp8, g_Cp8);
    u8*   dQp8; cudaGetSymbolAddress((void**)&dQp8, g_Qp8);
    bf16* dSb;  cudaGetSymbolAddress((void**)&dSb,  g_Sb);
    u8*   dP8;  cudaGetSymbolAddress((void**)&dP8,  g_P8);

    const int FINAL_SMEM = 9 * FCH * 16;   // 92160 B
    cudaFuncSetAttribute(final_fp8,
                         cudaFuncAttributeMaxDynamicSharedMemorySize, FINAL_SMEM);

    compact_kernel<<<NB, 256>>>(Cmask);
    fill_masked_kernel<<<dim3(1, LC, NB), 128>>>(Cmask, out);

    // one-time fp32 -> e4m3 conversions
    cvt8_kernel<<<(NB * LC * DD / 16 + 255) / 256, 256>>>(C,  dC8,  NB * LC * DD / 16, 1.0f);
    cvt8_kernel<<<(NB * LQ * DD / 16 + 255) / 256, 256>>>(Q,  dQ8,  NB * LQ * DD / 16, 1.0f);
    cvt8_kernel<<<(DD * DD / 16 + 255) / 256, 256>>>(W1, dW18, DD * DD / 16, 16.0f);
    cvt8_kernel<<<(D4 * D4 / 16 + 255) / 256, 256>>>(Wf, dWf8, D4 * D4 / 16, 16.0f);
    cvt8_kernel<<<(D4 * D4 / 16 + 255) / 256, 256>>>(Wg, dWg8, D4 * D4 / 16, 16.0f);
    transpose_q8_kernel<<<dim3(DD / 32, LQ / 32, NB), dim3(32, 8)>>>(Q);

    // C_ = lrelu(C@W1^T/16 + b1) x4 -> e4m3, compacted rows
    gemm_fp8<<<dim3(DD / 64, LC / 128, NB), 256>>>(
        dC8, DD, LC, dW18, DD, 0, dCp8, DD, b1, DD, LC, 1, 1, 0, W8INV, 4.0f);
    // Q_ likewise, all rows
    gemm_fp8<<<dim3(DD / 64, LQ / 128, NB), 256>>>(
        dQ8, DD, LQ, dW18, DD, 0, dQp8, DD, b1, DD, LQ, 0, 0, 0, W8INV, 4.0f);
    // S = (4C_)(4Q_)^T / 16 -> bf16 raw scores
    gemm_fp8<<<dim3(LQ / 64, LC / 128, NB), 256>>>(
        dCp8, DD, LC, dQp8, DD, LQ, dSb, LQ, b1, DD, LC, 1, 0, 2, W8INV, 1.0f);
    // masked softmax -> e4m3 probs x16
    softmax_kernel<<<dim3(LC, NB), 256>>>(Qmask);
    // attn_C = (16P)(16Qt)^T / 256 -> fused e4m3 cat write
    gemm_fp8<<<dim3(DD / 64, LC / 128, NB), 256>>>(
        dP8, LQ, LC, dQt8, LQ, DD, (void*)0, DD, b1, LQ, LC, 1, 0, 3,
        1.0f / 256.0f, 1.0f);
    // FP8 fused dual GEMM + blend epilogue
    final_fp8<<<dim3(D4 / 128, LC / 128, NB), 512, FINAL_SMEM>>>(bfv, bgv, out);
}